// round 9
// baseline (speedup 1.0000x reference)
#include <cuda_runtime.h>
#include <cuda_bf16.h>
#include <math.h>
#include <stdint.h>

// ---------------- problem constants ----------------
constexpr int B_  = 512;
constexpr int T_  = 200;
constexpr int D_  = 64;
constexpr int H_  = 256;
constexpr int BT  = B_ * T_;        // 102400 rows
constexpr int HT  = H_ * T_;        // 51200 flat dim
constexpr int C1_ = 1024;
constexpr int C2_ = 256;
constexpr int C3_ = 10;
constexpr int R1_ = 1024;
constexpr int G3  = 768;            // packed gates i,g,o (forget gate dead, c0=0)

constexpr size_t OUT_TOTAL_OFF = 0;
constexpr size_t OUT_CLASS_OFF = (size_t)BT * H_;
constexpr size_t OUT_REG_OFF   = OUT_CLASS_OFF + (size_t)B_ * C3_;

// ---------------- device scratch ----------------
__device__ __nv_bfloat16 g_w0h[G3 * D_],  g_w0l[G3 * D_];
__device__ __nv_bfloat16 g_w1h[G3 * H_],  g_w1l[G3 * H_];
__device__ float g_bsel0[G3], g_bsel1[G3];
__device__ __nv_bfloat16 g_xh[(size_t)BT * D_],  g_xl[(size_t)BT * D_];
__device__ __nv_bfloat16 g_h0h[(size_t)BT * H_], g_h0l[(size_t)BT * H_];
__device__ __nv_bfloat16 g_fh [(size_t)BT * H_], g_fl [(size_t)BT * H_];
__device__ __nv_bfloat16 g_f1h[(size_t)C1_ * HT], g_f1l[(size_t)C1_ * HT];
__device__ __nv_bfloat16 g_f4h[(size_t)R1_ * HT], g_f4l[(size_t)R1_ * HT];
__device__ float g_part[16 * 512 * 1024];   // split-K partials
__device__ float g_c1[B_ * C1_];
__device__ float g_c2[B_ * C2_];
__device__ float g_r [B_ * R1_];

// ---------------- PTX helpers (sm_80-compatible only) ----------------
__device__ __forceinline__ uint32_t smem_u32(const void* p) {
    uint32_t a;
    asm("{ .reg .u64 t; cvta.to.shared.u64 t, %1; cvt.u32.u64 %0, t; }" : "=r"(a) : "l"(p));
    return a;
}
__device__ __forceinline__ void cp_async16(uint32_t dst, const void* src) {
    asm volatile("cp.async.cg.shared.global [%0], [%1], 16;" :: "r"(dst), "l"(src));
}
#define CP_COMMIT() asm volatile("cp.async.commit_group;" ::: "memory")
template <int N>
__device__ __forceinline__ void cp_wait() {
    asm volatile("cp.async.wait_group %0;" :: "n"(N) : "memory");
}
__device__ __forceinline__ void ldsm_x4(uint32_t* r, uint32_t addr) {
    asm volatile("ldmatrix.sync.aligned.m8n8.x4.shared.b16 {%0,%1,%2,%3}, [%4];"
                 : "=r"(r[0]), "=r"(r[1]), "=r"(r[2]), "=r"(r[3]) : "r"(addr));
}
__device__ __forceinline__ void ldsm_x2(uint32_t* r, uint32_t addr) {
    asm volatile("ldmatrix.sync.aligned.m8n8.x2.shared.b16 {%0,%1}, [%2];"
                 : "=r"(r[0]), "=r"(r[1]) : "r"(addr));
}
__device__ __forceinline__ void mma_bf16(float* c, const uint32_t* a, const uint32_t* b) {
    asm volatile("mma.sync.aligned.m16n8k16.row.col.f32.bf16.bf16.f32 "
                 "{%0,%1,%2,%3}, {%4,%5,%6,%7}, {%8,%9}, {%0,%1,%2,%3};"
                 : "+f"(c[0]), "+f"(c[1]), "+f"(c[2]), "+f"(c[3])
                 : "r"(a[0]), "r"(a[1]), "r"(a[2]), "r"(a[3]), "r"(b[0]), "r"(b[1]));
}
__device__ __forceinline__ uint32_t pack_bf2(float a, float b) {
    __nv_bfloat162 t = __floats2bfloat162_rn(a, b);
    return *reinterpret_cast<uint32_t*>(&t);
}
__device__ __forceinline__ float bf_hi(float v) {
    __nv_bfloat16 h = __float2bfloat16(v);
    return __bfloat162float(h);
}
__device__ __forceinline__ float sigm(float x) { return 1.f / (1.f + expf(-x)); }

// ---------------- hi/lo HMMA GEMM (pre-split bf16 in) ----------------
// Standard mode: C[z][M,N] partial = (Ahi+Alo)[M,K] * (Bhi+Blo)[N,K]^T (3 terms).
// Gate mode: g in {i,g,o}: acc_g = A * Wsel[g*256+n,:]^T + bias; h composed in
//            REGISTER stash; writes optional fp32 C plus bf16 hi/lo out.
// Tile 128x128x64, 512 threads, warp grid 4x4, warp tile 32x32.
// 3-stage cp.async pipeline, tiles per stage: Ahi|Alo|Bhi|Blo.
constexpr int HS_ROWB  = 144;               // 64 bf16 + 8 pad, bytes
constexpr int HS_TILE  = 128 * HS_ROWB;     // 18432
constexpr int HS_STAGE = 4 * HS_TILE;       // 73728
constexpr int HS_SMEM  = 3 * HS_STAGE;      // 221184

__global__ void __launch_bounds__(512, 1)
hs_gemm(const __nv_bfloat16* __restrict__ Ahi, const __nv_bfloat16* __restrict__ Alo,
        const __nv_bfloat16* __restrict__ Bhi, const __nv_bfloat16* __restrict__ Blo,
        float* __restrict__ C, const float* __restrict__ bias,
        __nv_bfloat16* __restrict__ outHi, __nv_bfloat16* __restrict__ outLo,
        int M, int N, int K, int kSlice, int gateMode)
{
    extern __shared__ __align__(128) char smem[];
    const uint32_t sBase = smem_u32(smem);

    const int tid  = threadIdx.x;
    const int lane = tid & 31;
    const int warp = tid >> 5;
    const int wm   = warp >> 2;              // 0..3
    const int wn   = warp & 3;               // 0..3
    const int mBase = blockIdx.y * 128;
    const int nBase = blockIdx.x * 128;
    const int z     = gateMode ? 0 : blockIdx.z;
    const int kBeg  = z * kSlice;
    const int NC    = kSlice >> 6;

    const int aRow = (lane & 7) + ((lane >> 3) & 1) * 8;
    const int aCol = (lane >> 4) * 8;
    const int bRow = lane & 7;
    const int bCol = ((lane >> 3) & 1) * 8;

    // loader: per tile 1024 x 16B chunks; 512 threads -> 2 chunks/tile/thread
    const int lrow0 = tid >> 3;              // 0..63
    const int lrow1 = lrow0 + 64;            // 64..127
    const int lc8   = tid & 7;               // 16B unit in 128B row

    const int nGates = gateMode ? 3 : 1;

    float stash[2][4][4];                    // carries sigm(i), then sigm(i)*tanh(g)

    for (int g = 0; g < nGates; g++) {
        const int rowOff = gateMode ? (g * 256 + nBase) : nBase;

        float acc[2][4][4];
#pragma unroll
        for (int mi = 0; mi < 2; mi++)
#pragma unroll
            for (int ni = 0; ni < 4; ni++)
#pragma unroll
                for (int q = 0; q < 4; q++) acc[mi][ni][q] = 0.f;

        auto prefetch = [&](int c) {
            if (c < NC) {
                int kk = kBeg + c * 64;
                uint32_t st = sBase + (c % 3) * HS_STAGE;
                const __nv_bfloat16* srcs[4] = {
                    Ahi + (size_t)(mBase + 0) * K, Alo + (size_t)(mBase + 0) * K,
                    Bhi + (size_t)(rowOff + 0) * K, Blo + (size_t)(rowOff + 0) * K };
#pragma unroll
                for (int tI = 0; tI < 4; tI++) {
                    uint32_t base = st + tI * HS_TILE;
                    cp_async16(base + lrow0 * HS_ROWB + lc8 * 16,
                               srcs[tI] + (size_t)lrow0 * K + kk + lc8 * 8);
                    cp_async16(base + lrow1 * HS_ROWB + lc8 * 16,
                               srcs[tI] + (size_t)lrow1 * K + kk + lc8 * 8);
                }
            }
            CP_COMMIT();                      // unconditional: keeps group count fixed
        };

        prefetch(0); prefetch(1); prefetch(2);

        for (int c = 0; c < NC; c++) {
            cp_wait<2>();                    // group c complete (3 always in flight)
            __syncthreads();

            uint32_t sAhi = sBase + (c % 3) * HS_STAGE;
            uint32_t sAlo = sAhi + HS_TILE;
            uint32_t sBhi = sAhi + 2 * HS_TILE;
            uint32_t sBlo = sAhi + 3 * HS_TILE;
#pragma unroll
            for (int ks = 0; ks < 4; ks++) {
                uint32_t ah[2][4], al[2][4], bh[4][2], bl[4][2];
#pragma unroll
                for (int mi = 0; mi < 2; mi++) {
                    uint32_t ro = (wm * 32 + mi * 16 + aRow) * HS_ROWB + (ks * 16 + aCol) * 2;
                    ldsm_x4(ah[mi], sAhi + ro);
                    ldsm_x4(al[mi], sAlo + ro);
                }
#pragma unroll
                for (int ni = 0; ni < 4; ni++) {
                    uint32_t ro = (wn * 32 + ni * 8 + bRow) * HS_ROWB + (ks * 16 + bCol) * 2;
                    ldsm_x2(bh[ni], sBhi + ro);
                    ldsm_x2(bl[ni], sBlo + ro);
                }
#pragma unroll
                for (int mi = 0; mi < 2; mi++)
#pragma unroll
                    for (int ni = 0; ni < 4; ni++) {
                        mma_bf16(acc[mi][ni], ah[mi], bh[ni]);
                        mma_bf16(acc[mi][ni], ah[mi], bl[ni]);
                        mma_bf16(acc[mi][ni], al[mi], bh[ni]);
                    }
            }
            __syncthreads();                 // stage free before refill
            prefetch(c + 3);
        }

        // ---- epilogue ----
        if (!gateMode) {
            float* Cp = C + (size_t)z * M * N;
#pragma unroll
            for (int mi = 0; mi < 2; mi++) {
                int r0 = mBase + wm * 32 + mi * 16 + (lane >> 2);
#pragma unroll
                for (int ni = 0; ni < 4; ni++) {
                    int col = nBase + wn * 32 + ni * 8 + (lane & 3) * 2;
                    *reinterpret_cast<float2*>(&Cp[(size_t)r0 * N + col]) =
                        make_float2(acc[mi][ni][0], acc[mi][ni][1]);
                    *reinterpret_cast<float2*>(&Cp[(size_t)(r0 + 8) * N + col]) =
                        make_float2(acc[mi][ni][2], acc[mi][ni][3]);
                }
            }
        } else {
#pragma unroll
            for (int mi = 0; mi < 2; mi++)
#pragma unroll
                for (int ni = 0; ni < 4; ni++)
#pragma unroll
                    for (int q = 0; q < 4; q++) {
                        int rl = wm * 32 + mi * 16 + (lane >> 2) + ((q >= 2) ? 8 : 0);
                        int cl = wn * 32 + ni * 8 + (lane & 3) * 2 + (q & 1);
                        float v = acc[mi][ni][q] + bias[rowOff + cl];
                        if (g == 0)      stash[mi][ni][q] = sigm(v);
                        else if (g == 1) stash[mi][ni][q] *= tanhf(v);
                        else {
                            float h = sigm(v) * tanhf(stash[mi][ni][q]);
                            size_t o = (size_t)(mBase + rl) * H_ + nBase + cl;
                            if (C) C[o] = h;
                            float hh = bf_hi(h);
                            outHi[o] = __float2bfloat16(hh);
                            outLo[o] = __float2bfloat16(h - hh);
                        }
                    }
        }
    }
}

// ---------------- prep kernels ----------------
// fp32 -> (hi, lo) bf16, vectorized; n % 4 == 0
__global__ void split_f32(const float4* __restrict__ src, uint2* __restrict__ hi,
                          uint2* __restrict__ lo, int n4)
{
    int i = blockIdx.x * blockDim.x + threadIdx.x;
    if (i >= n4) return;
    float4 v = src[i];
    float hx = bf_hi(v.x), hy = bf_hi(v.y), hz = bf_hi(v.z), hw = bf_hi(v.w);
    hi[i] = make_uint2(pack_bf2(hx, hy), pack_bf2(hz, hw));
    lo[i] = make_uint2(pack_bf2(v.x - hx, v.y - hy), pack_bf2(v.z - hz, v.w - hw));
}

// pack gate rows {i, g, o} of W_ih -> split bf16; bsel = b_ih + b_hh
__global__ void make_wsel_split(const float* __restrict__ W, const float* __restrict__ bih,
                                const float* __restrict__ bhh, __nv_bfloat16* __restrict__ Whi,
                                __nv_bfloat16* __restrict__ Wlo, float* __restrict__ bsel, int Kd)
{
    int idx = blockIdx.x * blockDim.x + threadIdx.x;
    int total = G3 * Kd;
    if (idx < total) {
        int j = idx / Kd;
        int c = idx - j * Kd;
        int srcRow = j + ((j >= 256) ? 256 : 0);
        float v = W[srcRow * Kd + c];
        float h = bf_hi(v);
        Whi[idx] = __float2bfloat16(h);
        Wlo[idx] = __float2bfloat16(v - h);
    }
    if (idx < G3) {
        int srcRow = idx + ((idx >= 256) ? 256 : 0);
        bsel[idx] = bih[srcRow] + bhh[srcRow];
    }
}

__global__ void reduce_bias_act(const float* __restrict__ part, int S, int MN, int N,
                                const float* __restrict__ bias, float* __restrict__ out, int relu)
{
    int idx = blockIdx.x * blockDim.x + threadIdx.x;
    if (idx >= MN) return;
    float s = 0.f;
    for (int i = 0; i < S; i++) s += part[(size_t)i * MN + idx];
    s += bias[idx % N];
    if (relu) s = fmaxf(s, 0.f);
    out[idx] = s;
}

// ---------------- fp32 SGEMM (small fc layers) ----------------
__global__ void __launch_bounds__(256, 2)
sgemm_nt(const float* __restrict__ A, const float* __restrict__ B,
         float* __restrict__ C, int M, int N, int K, int kSlice)
{
    constexpr int BM = 128, BN = 128, BK = 8;
    __shared__ float As[BK][BM];
    __shared__ float Bs[BK][BN];
    const int tid = threadIdx.x;
    const int mBase = blockIdx.y * BM;
    const int nBase = blockIdx.x * BN;
    const int z = blockIdx.z;
    const int kBeg = z * kSlice;
    const int kEnd = kBeg + kSlice;
    const int lr = tid >> 1;
    const int lc = (tid & 1) * 4;
    const int tr = (tid >> 4) * 8;
    const int tc = (tid & 15) * 8;
    float acc[8][8];
#pragma unroll
    for (int i = 0; i < 8; i++)
#pragma unroll
        for (int j = 0; j < 8; j++) acc[i][j] = 0.f;
    const float* Aptr = A + (size_t)(mBase + lr) * K;
    const bool bvalid = (nBase + lr) < N;
    const float* Bptr = B + (bvalid ? (size_t)(nBase + lr) * K : 0);
    for (int k0 = kBeg; k0 < kEnd; k0 += BK) {
        float4 a4 = *reinterpret_cast<const float4*>(Aptr + k0 + lc);
        float4 b4 = make_float4(0.f, 0.f, 0.f, 0.f);
        if (bvalid) b4 = *reinterpret_cast<const float4*>(Bptr + k0 + lc);
        As[lc + 0][lr] = a4.x; As[lc + 1][lr] = a4.y;
        As[lc + 2][lr] = a4.z; As[lc + 3][lr] = a4.w;
        Bs[lc + 0][lr] = b4.x; Bs[lc + 1][lr] = b4.y;
        Bs[lc + 2][lr] = b4.z; Bs[lc + 3][lr] = b4.w;
        __syncthreads();
#pragma unroll
        for (int kk = 0; kk < BK; kk++) {
            float rm[8], rn[8];
#pragma unroll
            for (int i = 0; i < 8; i++) rm[i] = As[kk][tr + i];
#pragma unroll
            for (int j = 0; j < 8; j++) rn[j] = Bs[kk][tc + j];
#pragma unroll
            for (int i = 0; i < 8; i++)
#pragma unroll
                for (int j = 0; j < 8; j++) acc[i][j] = fmaf(rm[i], rn[j], acc[i][j]);
        }
        __syncthreads();
    }
    float* Cp = C + (size_t)z * M * N;
#pragma unroll
    for (int i = 0; i < 8; i++) {
        const size_t rowOff = (size_t)(mBase + tr + i) * N;
#pragma unroll
        for (int j = 0; j < 8; j++) {
            int col = nBase + tc + j;
            if (col < N) Cp[rowOff + col] = acc[i][j];
        }
    }
}

__global__ void fc3_kernel(const float* __restrict__ x, const float* __restrict__ W,
                           const float* __restrict__ b, float* __restrict__ out)
{
    int idx = blockIdx.x * blockDim.x + threadIdx.x;
    if (idx >= B_ * C3_) return;
    int m = idx / C3_;
    int n = idx - m * C3_;
    const float* xr = x + m * C2_;
    const float* wr = W + n * C2_;
    float s = 0.f;
#pragma unroll 4
    for (int k = 0; k < C2_; k++) s = fmaf(xr[k], wr[k], s);
    out[idx] = s + b[n];
}

// ---------------- launch ----------------
extern "C" void kernel_launch(void* const* d_in, const int* in_sizes, int n_in,
                              void* d_out_v, int out_size)
{
    const float* x     = (const float*)d_in[0];
    const float* W_ih0 = (const float*)d_in[1];
    const float* b_ih0 = (const float*)d_in[2];
    const float* b_hh0 = (const float*)d_in[3];
    const float* W_ih1 = (const float*)d_in[4];
    const float* b_ih1 = (const float*)d_in[5];
    const float* b_hh1 = (const float*)d_in[6];
    const float* fc1_w = (const float*)d_in[7];
    const float* fc1_b = (const float*)d_in[8];
    const float* fc2_w = (const float*)d_in[9];
    const float* fc2_b = (const float*)d_in[10];
    const float* fc3_w = (const float*)d_in[11];
    const float* fc3_b = (const float*)d_in[12];
    const float* fc4_w = (const float*)d_in[13];
    const float* fc4_b = (const float*)d_in[14];
    const float* fc5_w = (const float*)d_in[15];
    const float* fc5_b = (const float*)d_in[16];
    float* d_out = (float*)d_out_v;

    cudaFuncSetAttribute(hs_gemm, cudaFuncAttributeMaxDynamicSharedMemorySize, HS_SMEM);

    __nv_bfloat16 *w0h, *w0l, *w1h, *w1l, *xh, *xl, *h0h, *h0l, *fh, *fl, *f1h, *f1l, *f4h, *f4l;
    float *bsel0, *bsel1, *part, *c1, *c2, *r;
    cudaGetSymbolAddress((void**)&w0h, g_w0h);   cudaGetSymbolAddress((void**)&w0l, g_w0l);
    cudaGetSymbolAddress((void**)&w1h, g_w1h);   cudaGetSymbolAddress((void**)&w1l, g_w1l);
    cudaGetSymbolAddress((void**)&bsel0, g_bsel0); cudaGetSymbolAddress((void**)&bsel1, g_bsel1);
    cudaGetSymbolAddress((void**)&xh, g_xh);     cudaGetSymbolAddress((void**)&xl, g_xl);
    cudaGetSymbolAddress((void**)&h0h, g_h0h);   cudaGetSymbolAddress((void**)&h0l, g_h0l);
    cudaGetSymbolAddress((void**)&fh, g_fh);     cudaGetSymbolAddress((void**)&fl, g_fl);
    cudaGetSymbolAddress((void**)&f1h, g_f1h);   cudaGetSymbolAddress((void**)&f1l, g_f1l);
    cudaGetSymbolAddress((void**)&f4h, g_f4h);   cudaGetSymbolAddress((void**)&f4l, g_f4l);
    cudaGetSymbolAddress((void**)&part, g_part);
    cudaGetSymbolAddress((void**)&c1, g_c1);
    cudaGetSymbolAddress((void**)&c2, g_c2);
    cudaGetSymbolAddress((void**)&r, g_r);

    // prep: pack+split weights, split x and fc weights (one-time cost)
    make_wsel_split<<<(G3 * D_ + 255) / 256, 256>>>(W_ih0, b_ih0, b_hh0, w0h, w0l, bsel0, D_);
    make_wsel_split<<<(G3 * H_ + 255) / 256, 256>>>(W_ih1, b_ih1, b_hh1, w1h, w1l, bsel1, H_);
    split_f32<<<(BT * D_ / 4 + 255) / 256, 256>>>((const float4*)x, (uint2*)xh, (uint2*)xl, BT * D_ / 4);
    split_f32<<<(C1_ * HT / 4 + 255) / 256, 256>>>((const float4*)fc1_w, (uint2*)f1h, (uint2*)f1l, C1_ * HT / 4);
    split_f32<<<(R1_ * HT / 4 + 255) / 256, 256>>>((const float4*)fc4_w, (uint2*)f4h, (uint2*)f4l, R1_ * HT / 4);

    // LSTM layer 0 (gate mode): h0 (hi/lo) = lstm(x @ Wsel0^T + bsel0)
    hs_gemm<<<dim3(2, BT / 128, 1), 512, HS_SMEM>>>(
        xh, xl, w0h, w0l, nullptr, bsel0, h0h, h0l, BT, H_, D_, D_, 1);

    // LSTM layer 1 (gate mode): out_total fp32 -> d_out, flat hi/lo -> fh/fl
    hs_gemm<<<dim3(2, BT / 128, 1), 512, HS_SMEM>>>(
        h0h, h0l, w1h, w1l, d_out + OUT_TOTAL_OFF, bsel1, fh, fl, BT, H_, H_, H_, 1);

    // fc1 (split-K=16) + relu
    hs_gemm<<<dim3(C1_ / 128, B_ / 128, 16), 512, HS_SMEM>>>(
        fh, fl, f1h, f1l, part, nullptr, nullptr, nullptr, B_, C1_, HT, HT / 16, 0);
    reduce_bias_act<<<(B_ * C1_ + 255) / 256, 256>>>(part, 16, B_ * C1_, C1_, fc1_b, c1, 1);

    // fc2 (fp32 path) + relu
    sgemm_nt<<<dim3(C2_ / 128, B_ / 128, 4), 256>>>(c1, fc2_w, part, B_, C2_, C1_, C1_ / 4);
    reduce_bias_act<<<(B_ * C2_ + 255) / 256, 256>>>(part, 4, B_ * C2_, C2_, fc2_b, c2, 1);

    // fc3 -> class output
    fc3_kernel<<<(B_ * C3_ + 255) / 256, 256>>>(c2, fc3_w, fc3_b, d_out + OUT_CLASS_OFF);

    // fc4 (split-K=16) + relu
    hs_gemm<<<dim3(R1_ / 128, B_ / 128, 16), 512, HS_SMEM>>>(
        fh, fl, f4h, f4l, part, nullptr, nullptr, nullptr, B_, R1_, HT, HT / 16, 0);
    reduce_bias_act<<<(B_ * R1_ + 255) / 256, 256>>>(part, 16, B_ * R1_, R1_, fc4_b, r, 1);

    // fc5 (fp32 path, N=200 ragged) -> regression output
    sgemm_nt<<<dim3((T_ + 127) / 128, B_ / 128, 4), 256>>>(r, fc5_w, part, B_, T_, R1_, R1_ / 4);
    reduce_bias_act<<<(B_ * T_ + 255) / 256, 256>>>(part, 4, B_ * T_, T_, fc5_b,
                                                    d_out + OUT_REG_OFF, 0);
}

// round 10
// speedup vs baseline: 1.0489x; 1.0489x over previous
#include <cuda_runtime.h>
#include <cuda_bf16.h>
#include <math.h>
#include <stdint.h>

// ---------------- problem constants ----------------
constexpr int B_  = 512;
constexpr int T_  = 200;
constexpr int D_  = 64;
constexpr int H_  = 256;
constexpr int BT  = B_ * T_;        // 102400 rows
constexpr int HT  = H_ * T_;        // 51200 flat dim
constexpr int C1_ = 1024;
constexpr int C2_ = 256;
constexpr int C3_ = 10;
constexpr int R1_ = 1024;
constexpr int G3  = 768;            // packed gates i,g,o (forget gate dead, c0=0)

constexpr size_t OUT_TOTAL_OFF = 0;
constexpr size_t OUT_CLASS_OFF = (size_t)BT * H_;
constexpr size_t OUT_REG_OFF   = OUT_CLASS_OFF + (size_t)B_ * C3_;

// ---------------- device scratch ----------------
__device__ float g_wsel0[G3 * D_];          // packed i,g,o rows fp32
__device__ float g_wsel1[G3 * H_];
__device__ float g_bsel0[G3], g_bsel1[G3];
__device__ float g_h0[(size_t)BT * H_];     // 105 MB fp32
__device__ float g_part[16 * 512 * 1024];   // split-K partials
__device__ float g_c1[B_ * C1_];
__device__ float g_c2[B_ * C2_];
__device__ float g_r [B_ * R1_];

// ---------------- PTX helpers (sm_80-compatible only) ----------------
__device__ __forceinline__ uint32_t smem_u32(const void* p) {
    uint32_t a;
    asm("{ .reg .u64 t; cvta.to.shared.u64 t, %1; cvt.u32.u64 %0, t; }" : "=r"(a) : "l"(p));
    return a;
}
__device__ __forceinline__ void ldsm_x4(uint32_t* r, uint32_t addr) {
    asm volatile("ldmatrix.sync.aligned.m8n8.x4.shared.b16 {%0,%1,%2,%3}, [%4];"
                 : "=r"(r[0]), "=r"(r[1]), "=r"(r[2]), "=r"(r[3]) : "r"(addr));
}
__device__ __forceinline__ void mma_bf16(float* c, const uint32_t* a, const uint32_t* b) {
    asm volatile("mma.sync.aligned.m16n8k16.row.col.f32.bf16.bf16.f32 "
                 "{%0,%1,%2,%3}, {%4,%5,%6,%7}, {%8,%9}, {%0,%1,%2,%3};"
                 : "+f"(c[0]), "+f"(c[1]), "+f"(c[2]), "+f"(c[3])
                 : "r"(a[0]), "r"(a[1]), "r"(a[2]), "r"(a[3]), "r"(b[0]), "r"(b[1]));
}
__device__ __forceinline__ uint32_t pack_bf2(float a, float b) {
    __nv_bfloat162 t = __floats2bfloat162_rn(a, b);
    return *reinterpret_cast<uint32_t*>(&t);
}
__device__ __forceinline__ float bf_hi(float v) {
    __nv_bfloat16 h = __float2bfloat16(v);
    return __bfloat162float(h);
}
__device__ __forceinline__ float sigm(float x) { return 1.f / (1.f + expf(-x)); }

// ---------------- hi/lo-split HMMA GEMM (fp32 in, fp32 out) ----------------
// Standard mode: C[z][M,N] partial = A[M,K] * B[N,K]^T over k-slice z (3 bf16 terms).
// Gate mode: g in {i,g,o}: acc_g = A * Wsel[g*256+n,:]^T + bias; h via register
//            stash; writes h[M,256] fp32.
// Block tile 128x64x64, 256 threads, warp grid 4x2, warp tile 32x32.
// Two-stage SMEM, two syncs per chunk; occupancy 2 CTAs/SM gives phase overlap.
constexpr int HS_ROWB  = 144;                  // 64 bf16 + 8 pad, bytes
constexpr int HS_ATILE = 128 * HS_ROWB;        // 18432
constexpr int HS_BTILE = 64 * HS_ROWB;         // 9216
constexpr int HS_STAGE = 2 * HS_ATILE + 2 * HS_BTILE;   // 55296
constexpr int HS_SMEM  = 2 * HS_STAGE;         // 110592 (x2 CTAs = 221184/SM)

__global__ void __launch_bounds__(256, 2)
hs_gemm(const float* __restrict__ A, const float* __restrict__ Bw,
        float* __restrict__ C, const float* __restrict__ bias,
        int M, int N, int K, int kSlice, int gateMode)
{
    extern __shared__ __align__(128) char smem[];
    const uint32_t sBase = smem_u32(smem);

    const int tid  = threadIdx.x;
    const int lane = tid & 31;
    const int warp = tid >> 5;
    const int wm   = warp >> 1;              // 0..3
    const int wn   = warp & 1;               // 0..1
    const int mBase = blockIdx.y * 128;
    const int nBase = blockIdx.x * 64;
    const int z     = gateMode ? 0 : blockIdx.z;
    const int kBeg  = z * kSlice;
    const int NC    = kSlice >> 6;

    const int aRow  = (lane & 7) + ((lane >> 3) & 1) * 8;
    const int aCol  = (lane >> 4) * 8;
    const int bRow4 = ((lane >> 4) & 1) * 8 + (lane & 7);   // paired-x4 B row
    const int bColH = ((lane >> 3) & 1) * 8;                // k-half select

    // loader indices: A 2048 float4 -> 8/thread; B 1024 float4 -> 4/thread
    int arow[8], ac4[8], brow[4], bc4[4];
#pragma unroll
    for (int t = 0; t < 8; t++) { int idx = tid + t * 256; arow[t] = idx >> 4; ac4[t] = idx & 15; }
#pragma unroll
    for (int t = 0; t < 4; t++) { int idx = tid + t * 256; brow[t] = idx >> 4; bc4[t] = idx & 15; }

    const int nGates = gateMode ? 3 : 1;
    float stash[2][4][4];

    for (int g = 0; g < nGates; g++) {
        const int rowOff = gateMode ? (g * 256 + nBase) : nBase;

        float acc[2][4][4];
#pragma unroll
        for (int mi = 0; mi < 2; mi++)
#pragma unroll
            for (int ni = 0; ni < 4; ni++)
#pragma unroll
                for (int q = 0; q < 4; q++) acc[mi][ni][q] = 0.f;

        float4 aR[8], bR[4];
        auto ldg_chunk = [&](int c) {
            int kk = kBeg + c * 64;
#pragma unroll
            for (int t = 0; t < 8; t++)
                aR[t] = *reinterpret_cast<const float4*>(A + (size_t)(mBase + arow[t]) * K + kk + ac4[t] * 4);
#pragma unroll
            for (int t = 0; t < 4; t++)
                bR[t] = *reinterpret_cast<const float4*>(Bw + (size_t)(rowOff + brow[t]) * K + kk + bc4[t] * 4);
        };
        auto sts_split = [&](int stage) {
            char* pAhi = smem + stage * HS_STAGE;
            char* pAlo = pAhi + HS_ATILE;
            char* pBhi = pAhi + 2 * HS_ATILE;
            char* pBlo = pBhi + HS_BTILE;
#pragma unroll
            for (int t = 0; t < 8; t++) {
                int off = arow[t] * HS_ROWB + ac4[t] * 8;
                float4 v = aR[t];
                float hx = bf_hi(v.x), hy = bf_hi(v.y), hz = bf_hi(v.z), hw = bf_hi(v.w);
                *reinterpret_cast<uint2*>(pAhi + off) =
                    make_uint2(pack_bf2(hx, hy), pack_bf2(hz, hw));
                *reinterpret_cast<uint2*>(pAlo + off) =
                    make_uint2(pack_bf2(v.x - hx, v.y - hy), pack_bf2(v.z - hz, v.w - hw));
            }
#pragma unroll
            for (int t = 0; t < 4; t++) {
                int off = brow[t] * HS_ROWB + bc4[t] * 8;
                float4 v = bR[t];
                float hx = bf_hi(v.x), hy = bf_hi(v.y), hz = bf_hi(v.z), hw = bf_hi(v.w);
                *reinterpret_cast<uint2*>(pBhi + off) =
                    make_uint2(pack_bf2(hx, hy), pack_bf2(hz, hw));
                *reinterpret_cast<uint2*>(pBlo + off) =
                    make_uint2(pack_bf2(v.x - hx, v.y - hy), pack_bf2(v.z - hz, v.w - hw));
            }
        };

        ldg_chunk(0);
        for (int c = 0; c < NC; c++) {
            __syncthreads();                 // prior MMA done before overwrite
            sts_split(c & 1);
            __syncthreads();
            if (c + 1 < NC) ldg_chunk(c + 1);

            uint32_t sAhi = sBase + (c & 1) * HS_STAGE;
            uint32_t sAlo = sAhi + HS_ATILE;
            uint32_t sBhi = sAhi + 2 * HS_ATILE;
            uint32_t sBlo = sBhi + HS_BTILE;
#pragma unroll
            for (int ks = 0; ks < 4; ks++) {
                uint32_t ah[2][4], al[2][4], bh[2][4], bl[2][4];
#pragma unroll
                for (int mi = 0; mi < 2; mi++) {
                    uint32_t ro = (wm * 32 + mi * 16 + aRow) * HS_ROWB + (ks * 16 + aCol) * 2;
                    ldsm_x4(ah[mi], sAhi + ro);
                    ldsm_x4(al[mi], sAlo + ro);
                }
#pragma unroll
                for (int p = 0; p < 2; p++) {
                    uint32_t ro = (wn * 32 + p * 16 + bRow4) * HS_ROWB + (ks * 16 + bColH) * 2;
                    ldsm_x4(bh[p], sBhi + ro);
                    ldsm_x4(bl[p], sBlo + ro);
                }
#pragma unroll
                for (int mi = 0; mi < 2; mi++)
#pragma unroll
                    for (int ni = 0; ni < 4; ni++) {
                        const uint32_t* bhf = &bh[ni >> 1][(ni & 1) * 2];
                        const uint32_t* blf = &bl[ni >> 1][(ni & 1) * 2];
                        mma_bf16(acc[mi][ni], ah[mi], bhf);
                        mma_bf16(acc[mi][ni], ah[mi], blf);
                        mma_bf16(acc[mi][ni], al[mi], bhf);
                    }
            }
        }

        // ---- epilogue ----
        if (!gateMode) {
            float* Cp = C + (size_t)z * M * N;
#pragma unroll
            for (int mi = 0; mi < 2; mi++) {
                int r0 = mBase + wm * 32 + mi * 16 + (lane >> 2);
#pragma unroll
                for (int ni = 0; ni < 4; ni++) {
                    int col = nBase + wn * 32 + ni * 8 + (lane & 3) * 2;
                    *reinterpret_cast<float2*>(&Cp[(size_t)r0 * N + col]) =
                        make_float2(acc[mi][ni][0], acc[mi][ni][1]);
                    *reinterpret_cast<float2*>(&Cp[(size_t)(r0 + 8) * N + col]) =
                        make_float2(acc[mi][ni][2], acc[mi][ni][3]);
                }
            }
        } else {
#pragma unroll
            for (int mi = 0; mi < 2; mi++)
#pragma unroll
                for (int ni = 0; ni < 4; ni++)
#pragma unroll
                    for (int q = 0; q < 4; q++) {
                        int rl = wm * 32 + mi * 16 + (lane >> 2) + ((q >= 2) ? 8 : 0);
                        int cl = wn * 32 + ni * 8 + (lane & 3) * 2 + (q & 1);
                        float v = acc[mi][ni][q] + bias[rowOff + cl];
                        if (g == 0)      stash[mi][ni][q] = sigm(v);
                        else if (g == 1) stash[mi][ni][q] *= tanhf(v);
                        else {
                            float h = sigm(v) * tanhf(stash[mi][ni][q]);
                            C[(size_t)(mBase + rl) * H_ + nBase + cl] = h;
                        }
                    }
        }
    }
}

// ---------------- small kernels ----------------
__global__ void make_wsel(const float* __restrict__ W, const float* __restrict__ bih,
                          const float* __restrict__ bhh, float* __restrict__ Wsel,
                          float* __restrict__ bsel, int Kd)
{
    int idx = blockIdx.x * blockDim.x + threadIdx.x;
    int total = G3 * Kd;
    if (idx < total) {
        int j = idx / Kd;
        int c = idx - j * Kd;
        int src = j + ((j >= 256) ? 256 : 0);
        Wsel[idx] = W[src * Kd + c];
    }
    if (idx < G3) {
        int src = idx + ((idx >= 256) ? 256 : 0);
        bsel[idx] = bih[src] + bhh[src];
    }
}

__global__ void reduce_bias_act(const float* __restrict__ part, int S, int MN, int N,
                                const float* __restrict__ bias, float* __restrict__ out, int relu)
{
    int idx = blockIdx.x * blockDim.x + threadIdx.x;
    if (idx >= MN) return;
    float s = 0.f;
    for (int i = 0; i < S; i++) s += part[(size_t)i * MN + idx];
    s += bias[idx % N];
    if (relu) s = fmaxf(s, 0.f);
    out[idx] = s;
}

// ---------------- fp32 SGEMM (small fc layers) ----------------
__global__ void __launch_bounds__(256, 2)
sgemm_nt(const float* __restrict__ A, const float* __restrict__ B,
         float* __restrict__ C, int M, int N, int K, int kSlice)
{
    constexpr int BM = 128, BN = 128, BK = 8;
    __shared__ float As[BK][BM];
    __shared__ float Bs[BK][BN];
    const int tid = threadIdx.x;
    const int mBase = blockIdx.y * BM;
    const int nBase = blockIdx.x * BN;
    const int z = blockIdx.z;
    const int kBeg = z * kSlice;
    const int kEnd = kBeg + kSlice;
    const int lr = tid >> 1;
    const int lc = (tid & 1) * 4;
    const int tr = (tid >> 4) * 8;
    const int tc = (tid & 15) * 8;
    float acc[8][8];
#pragma unroll
    for (int i = 0; i < 8; i++)
#pragma unroll
        for (int j = 0; j < 8; j++) acc[i][j] = 0.f;
    const float* Aptr = A + (size_t)(mBase + lr) * K;
    const bool bvalid = (nBase + lr) < N;
    const float* Bptr = B + (bvalid ? (size_t)(nBase + lr) * K : 0);
    for (int k0 = kBeg; k0 < kEnd; k0 += BK) {
        float4 a4 = *reinterpret_cast<const float4*>(Aptr + k0 + lc);
        float4 b4 = make_float4(0.f, 0.f, 0.f, 0.f);
        if (bvalid) b4 = *reinterpret_cast<const float4*>(Bptr + k0 + lc);
        As[lc + 0][lr] = a4.x; As[lc + 1][lr] = a4.y;
        As[lc + 2][lr] = a4.z; As[lc + 3][lr] = a4.w;
        Bs[lc + 0][lr] = b4.x; Bs[lc + 1][lr] = b4.y;
        Bs[lc + 2][lr] = b4.z; Bs[lc + 3][lr] = b4.w;
        __syncthreads();
#pragma unroll
        for (int kk = 0; kk < BK; kk++) {
            float rm[8], rn[8];
#pragma unroll
            for (int i = 0; i < 8; i++) rm[i] = As[kk][tr + i];
#pragma unroll
            for (int j = 0; j < 8; j++) rn[j] = Bs[kk][tc + j];
#pragma unroll
            for (int i = 0; i < 8; i++)
#pragma unroll
                for (int j = 0; j < 8; j++) acc[i][j] = fmaf(rm[i], rn[j], acc[i][j]);
        }
        __syncthreads();
    }
    float* Cp = C + (size_t)z * M * N;
#pragma unroll
    for (int i = 0; i < 8; i++) {
        const size_t rowOff = (size_t)(mBase + tr + i) * N;
#pragma unroll
        for (int j = 0; j < 8; j++) {
            int col = nBase + tc + j;
            if (col < N) Cp[rowOff + col] = acc[i][j];
        }
    }
}

__global__ void fc3_kernel(const float* __restrict__ x, const float* __restrict__ W,
                           const float* __restrict__ b, float* __restrict__ out)
{
    int idx = blockIdx.x * blockDim.x + threadIdx.x;
    if (idx >= B_ * C3_) return;
    int m = idx / C3_;
    int n = idx - m * C3_;
    const float* xr = x + m * C2_;
    const float* wr = W + n * C2_;
    float s = 0.f;
#pragma unroll 4
    for (int k = 0; k < C2_; k++) s = fmaf(xr[k], wr[k], s);
    out[idx] = s + b[n];
}

// ---------------- launch ----------------
extern "C" void kernel_launch(void* const* d_in, const int* in_sizes, int n_in,
                              void* d_out_v, int out_size)
{
    const float* x     = (const float*)d_in[0];
    const float* W_ih0 = (const float*)d_in[1];
    const float* b_ih0 = (const float*)d_in[2];
    const float* b_hh0 = (const float*)d_in[3];
    const float* W_ih1 = (const float*)d_in[4];
    const float* b_ih1 = (const float*)d_in[5];
    const float* b_hh1 = (const float*)d_in[6];
    const float* fc1_w = (const float*)d_in[7];
    const float* fc1_b = (const float*)d_in[8];
    const float* fc2_w = (const float*)d_in[9];
    const float* fc2_b = (const float*)d_in[10];
    const float* fc3_w = (const float*)d_in[11];
    const float* fc3_b = (const float*)d_in[12];
    const float* fc4_w = (const float*)d_in[13];
    const float* fc4_b = (const float*)d_in[14];
    const float* fc5_w = (const float*)d_in[15];
    const float* fc5_b = (const float*)d_in[16];
    float* d_out = (float*)d_out_v;

    cudaFuncSetAttribute(hs_gemm, cudaFuncAttributeMaxDynamicSharedMemorySize, HS_SMEM);

    float *wsel0, *wsel1, *bsel0, *bsel1, *h0, *part, *c1, *c2, *r;
    cudaGetSymbolAddress((void**)&wsel0, g_wsel0);
    cudaGetSymbolAddress((void**)&wsel1, g_wsel1);
    cudaGetSymbolAddress((void**)&bsel0, g_bsel0);
    cudaGetSymbolAddress((void**)&bsel1, g_bsel1);
    cudaGetSymbolAddress((void**)&h0,    g_h0);
    cudaGetSymbolAddress((void**)&part,  g_part);
    cudaGetSymbolAddress((void**)&c1,    g_c1);
    cudaGetSymbolAddress((void**)&c2,    g_c2);
    cudaGetSymbolAddress((void**)&r,     g_r);

    // pack gate weights (fp32, skip forget gate)
    make_wsel<<<(G3 * D_ + 255) / 256, 256>>>(W_ih0, b_ih0, b_hh0, wsel0, bsel0, D_);
    make_wsel<<<(G3 * H_ + 255) / 256, 256>>>(W_ih1, b_ih1, b_hh1, wsel1, bsel1, H_);

    // LSTM layer 0 (gate mode): h0 = lstm(x @ Wsel0^T + bsel0)
    hs_gemm<<<dim3(H_ / 64, BT / 128, 1), 256, HS_SMEM>>>(
        x, wsel0, h0, bsel0, BT, H_, D_, D_, 1);

    // LSTM layer 1 (gate mode): out_total = lstm(h0 @ Wsel1^T + bsel1) -> d_out
    hs_gemm<<<dim3(H_ / 64, BT / 128, 1), 256, HS_SMEM>>>(
        h0, wsel1, d_out + OUT_TOTAL_OFF, bsel1, BT, H_, H_, H_, 1);

    const float* flat = d_out + OUT_TOTAL_OFF;  // [512, 51200] fp32

    // fc1 (split-K=16) + relu
    hs_gemm<<<dim3(C1_ / 64, B_ / 128, 16), 256, HS_SMEM>>>(
        flat, fc1_w, part, nullptr, B_, C1_, HT, HT / 16, 0);
    reduce_bias_act<<<(B_ * C1_ + 255) / 256, 256>>>(part, 16, B_ * C1_, C1_, fc1_b, c1, 1);

    // fc2 (fp32 path) + relu
    sgemm_nt<<<dim3(C2_ / 128, B_ / 128, 4), 256>>>(c1, fc2_w, part, B_, C2_, C1_, C1_ / 4);
    reduce_bias_act<<<(B_ * C2_ + 255) / 256, 256>>>(part, 4, B_ * C2_, C2_, fc2_b, c2, 1);

    // fc3 -> class output
    fc3_kernel<<<(B_ * C3_ + 255) / 256, 256>>>(c2, fc3_w, fc3_b, d_out + OUT_CLASS_OFF);

    // fc4 (split-K=16) + relu
    hs_gemm<<<dim3(R1_ / 64, B_ / 128, 16), 256, HS_SMEM>>>(
        flat, fc4_w, part, nullptr, B_, R1_, HT, HT / 16, 0);
    reduce_bias_act<<<(B_ * R1_ + 255) / 256, 256>>>(part, 16, B_ * R1_, R1_, fc4_b, r, 1);

    // fc5 (fp32 path, N=200 ragged) -> regression output
    sgemm_nt<<<dim3((T_ + 127) / 128, B_ / 128, 4), 256>>>(r, fc5_w, part, B_, T_, R1_, R1_ / 4);
    reduce_bias_act<<<(B_ * T_ + 255) / 256, 256>>>(part, 4, B_ * T_, T_, fc5_b,
                                                    d_out + OUT_REG_OFF, 0);
}

// round 11
// speedup vs baseline: 1.5633x; 1.4904x over previous
#include <cuda_runtime.h>
#include <cuda_fp16.h>
#include <math.h>
#include <stdint.h>

// ---------------- problem constants ----------------
constexpr int B_  = 512;
constexpr int T_  = 200;
constexpr int D_  = 64;
constexpr int H_  = 256;
constexpr int BT  = B_ * T_;        // 102400 rows
constexpr int HT  = H_ * T_;        // 51200 flat dim
constexpr int C1_ = 1024;
constexpr int C2_ = 256;
constexpr int C3_ = 10;
constexpr int R1_ = 1024;
constexpr int G3  = 768;            // packed gates i,g,o (forget gate dead, c0=0)

constexpr size_t OUT_TOTAL_OFF = 0;
constexpr size_t OUT_CLASS_OFF = (size_t)BT * H_;
constexpr size_t OUT_REG_OFF   = OUT_CLASS_OFF + (size_t)B_ * C3_;

// ---------------- device scratch ----------------
__device__ float g_wsel0[G3 * D_];          // packed i,g,o rows fp32
__device__ float g_wsel1[G3 * H_];
__device__ float g_bsel0[G3], g_bsel1[G3];
__device__ float g_h0[(size_t)BT * H_];     // 105 MB fp32
__device__ float g_part[16 * 512 * 1024];   // split-K partials
__device__ float g_c1[B_ * C1_];
__device__ float g_c2[B_ * C2_];
__device__ float g_r [B_ * R1_];

// ---------------- PTX helpers (sm_80-compatible only) ----------------
__device__ __forceinline__ uint32_t smem_u32(const void* p) {
    uint32_t a;
    asm("{ .reg .u64 t; cvta.to.shared.u64 t, %1; cvt.u32.u64 %0, t; }" : "=r"(a) : "l"(p));
    return a;
}
__device__ __forceinline__ void ldsm_x4(uint32_t* r, uint32_t addr) {
    asm volatile("ldmatrix.sync.aligned.m8n8.x4.shared.b16 {%0,%1,%2,%3}, [%4];"
                 : "=r"(r[0]), "=r"(r[1]), "=r"(r[2]), "=r"(r[3]) : "r"(addr));
}
__device__ __forceinline__ void mma_f16(float* c, const uint32_t* a, const uint32_t* b) {
    asm volatile("mma.sync.aligned.m16n8k16.row.col.f32.f16.f16.f32 "
                 "{%0,%1,%2,%3}, {%4,%5,%6,%7}, {%8,%9}, {%0,%1,%2,%3};"
                 : "+f"(c[0]), "+f"(c[1]), "+f"(c[2]), "+f"(c[3])
                 : "r"(a[0]), "r"(a[1]), "r"(a[2]), "r"(a[3]), "r"(b[0]), "r"(b[1]));
}
__device__ __forceinline__ uint32_t pack_h2(float a, float b) {
    __half2 t = __floats2half2_rn(a, b);
    return *reinterpret_cast<uint32_t*>(&t);
}
__device__ __forceinline__ float h_hi(float v) {
    return __half2float(__float2half_rn(v));
}
__device__ __forceinline__ float sigm(float x) { return 1.f / (1.f + expf(-x)); }

// ---------------- fp16 2-pass split HMMA GEMM (fp32 in, fp32 out) ----------------
// C ~= (A_hi + A_lo) * fp16(B)^T  (A split into hi/lo fp16, B rounded to fp16;
// dropped term ~2^-12 relative, incoherent over K).
// Standard mode: C[z][M,N] partial over k-slice z.
// Gate mode: g in {i,g,o}: acc_g = A * Wsel[g*256+n,:]^T + bias; h via SMEM stash.
// Tile 128x128x64, 512 threads, warp grid 4x4, warp tile 32x32.
// Single operand buffer, two syncs per chunk (R6 structure — best measured).
constexpr int HS_ROWB  = 144;               // 64 fp16 + 8 pad, bytes
constexpr int HS_TILE  = 128 * HS_ROWB;     // 18432
constexpr int HS_OPER  = 3 * HS_TILE;       // 55296 (A_hi | A_lo | B_hi)
constexpr int HS_STASH = 128 * 132 * 4;     // 67584 (128x128 fp32, pad)
constexpr int HS_SMEM_GATE = HS_OPER + HS_STASH;   // 122880

__global__ void __launch_bounds__(512, 1)
hs_gemm(const float* __restrict__ A, const float* __restrict__ Bw,
        float* __restrict__ C, const float* __restrict__ bias,
        int M, int N, int K, int kSlice, int gateMode)
{
    extern __shared__ __align__(128) char smem[];
    char* pAhi = smem;
    char* pAlo = smem + HS_TILE;
    char* pBhi = smem + 2 * HS_TILE;
    float* stash = reinterpret_cast<float*>(smem + HS_OPER);
    const uint32_t sAhi = smem_u32(pAhi);
    const uint32_t sAlo = sAhi + HS_TILE;
    const uint32_t sBhi = sAhi + 2 * HS_TILE;

    const int tid  = threadIdx.x;
    const int lane = tid & 31;
    const int warp = tid >> 5;
    const int wm   = warp >> 2;              // 0..3
    const int wn   = warp & 3;               // 0..3
    const int mBase = blockIdx.y * 128;
    const int nBase = blockIdx.x * 128;
    const int z     = gateMode ? 0 : blockIdx.z;
    const int kBeg  = z * kSlice;
    const int NC    = kSlice >> 6;

    const int aRow  = (lane & 7) + ((lane >> 3) & 1) * 8;
    const int aCol  = (lane >> 4) * 8;
    const int bRow4 = ((lane >> 4) & 1) * 8 + (lane & 7);   // paired-x4 B row
    const int bColH = ((lane >> 3) & 1) * 8;                // k-half select

    // loader: 2048 float4 per operand tile, 4 per thread
    int lr[4], lc4[4];
#pragma unroll
    for (int t = 0; t < 4; t++) {
        int idx = tid + t * 512;
        lr[t]  = idx >> 4;        // 0..127
        lc4[t] = idx & 15;        // float4 unit within 64-col row
    }

    const int nGates = gateMode ? 3 : 1;

    for (int g = 0; g < nGates; g++) {
        const int rowOff = gateMode ? (g * 256 + nBase) : nBase;

        float acc[2][4][4];
#pragma unroll
        for (int mi = 0; mi < 2; mi++)
#pragma unroll
            for (int ni = 0; ni < 4; ni++)
#pragma unroll
                for (int q = 0; q < 4; q++) acc[mi][ni][q] = 0.f;

        float4 aR[4], bR[4];

        auto ldg_chunk = [&](int c) {
            int kk = kBeg + c * 64;
#pragma unroll
            for (int t = 0; t < 4; t++) {
                aR[t] = *reinterpret_cast<const float4*>(A  + (size_t)(mBase + lr[t]) * K + kk + lc4[t] * 4);
                bR[t] = *reinterpret_cast<const float4*>(Bw + (size_t)(rowOff + lr[t]) * K + kk + lc4[t] * 4);
            }
        };
        auto sts_split = [&]() {
#pragma unroll
            for (int t = 0; t < 4; t++) {
                int off = lr[t] * HS_ROWB + lc4[t] * 8;
                float4 v = aR[t];
                float hx = h_hi(v.x), hy = h_hi(v.y), hz = h_hi(v.z), hw = h_hi(v.w);
                *reinterpret_cast<uint2*>(pAhi + off) =
                    make_uint2(pack_h2(hx, hy), pack_h2(hz, hw));
                *reinterpret_cast<uint2*>(pAlo + off) =
                    make_uint2(pack_h2(v.x - hx, v.y - hy), pack_h2(v.z - hz, v.w - hw));
                v = bR[t];
                *reinterpret_cast<uint2*>(pBhi + off) =
                    make_uint2(pack_h2(v.x, v.y), pack_h2(v.z, v.w));
            }
        };

        ldg_chunk(0);
        for (int c = 0; c < NC; c++) {
            __syncthreads();                 // prior MMA done before overwrite
            sts_split();
            __syncthreads();
            if (c + 1 < NC) ldg_chunk(c + 1);

#pragma unroll
            for (int ks = 0; ks < 4; ks++) {
                uint32_t ah[2][4], al[2][4], bh[2][4];
#pragma unroll
                for (int mi = 0; mi < 2; mi++) {
                    uint32_t ro = (wm * 32 + mi * 16 + aRow) * HS_ROWB + (ks * 16 + aCol) * 2;
                    ldsm_x4(ah[mi], sAhi + ro);
                    ldsm_x4(al[mi], sAlo + ro);
                }
#pragma unroll
                for (int p = 0; p < 2; p++) {
                    uint32_t ro = (wn * 32 + p * 16 + bRow4) * HS_ROWB + (ks * 16 + bColH) * 2;
                    ldsm_x4(bh[p], sBhi + ro);
                }
#pragma unroll
                for (int mi = 0; mi < 2; mi++)
#pragma unroll
                    for (int ni = 0; ni < 4; ni++) {
                        const uint32_t* bhf = &bh[ni >> 1][(ni & 1) * 2];
                        mma_f16(acc[mi][ni], ah[mi], bhf);
                        mma_f16(acc[mi][ni], al[mi], bhf);
                    }
            }
        }

        // ---- epilogue ----
        if (!gateMode) {
            float* Cp = C + (size_t)z * M * N;
#pragma unroll
            for (int mi = 0; mi < 2; mi++) {
                int r0 = mBase + wm * 32 + mi * 16 + (lane >> 2);
#pragma unroll
                for (int ni = 0; ni < 4; ni++) {
                    int col = nBase + wn * 32 + ni * 8 + (lane & 3) * 2;
                    *reinterpret_cast<float2*>(&Cp[(size_t)r0 * N + col]) =
                        make_float2(acc[mi][ni][0], acc[mi][ni][1]);
                    *reinterpret_cast<float2*>(&Cp[(size_t)(r0 + 8) * N + col]) =
                        make_float2(acc[mi][ni][2], acc[mi][ni][3]);
                }
            }
        } else {
#pragma unroll
            for (int mi = 0; mi < 2; mi++)
#pragma unroll
                for (int ni = 0; ni < 4; ni++)
#pragma unroll
                    for (int q = 0; q < 4; q++) {
                        int rl = wm * 32 + mi * 16 + (lane >> 2) + ((q >= 2) ? 8 : 0);
                        int cl = wn * 32 + ni * 8 + (lane & 3) * 2 + (q & 1);
                        float v = acc[mi][ni][q] + bias[rowOff + cl];
                        int si = rl * 132 + cl;
                        if (g == 0)      stash[si] = sigm(v);
                        else if (g == 1) stash[si] *= tanhf(v);
                        else {
                            float h = sigm(v) * tanhf(stash[si]);
                            C[(size_t)(mBase + rl) * H_ + nBase + cl] = h;
                        }
                    }
        }
    }
}

// ---------------- small kernels ----------------
__global__ void make_wsel(const float* __restrict__ W, const float* __restrict__ bih,
                          const float* __restrict__ bhh, float* __restrict__ Wsel,
                          float* __restrict__ bsel, int Kd)
{
    int idx = blockIdx.x * blockDim.x + threadIdx.x;
    int total = G3 * Kd;
    if (idx < total) {
        int j = idx / Kd;
        int c = idx - j * Kd;
        int src = j + ((j >= 256) ? 256 : 0);
        Wsel[idx] = W[src * Kd + c];
    }
    if (idx < G3) {
        int src = idx + ((idx >= 256) ? 256 : 0);
        bsel[idx] = bih[src] + bhh[src];
    }
}

__global__ void reduce_bias_act(const float* __restrict__ part, int S, int MN, int N,
                                const float* __restrict__ bias, float* __restrict__ out, int relu)
{
    int idx = blockIdx.x * blockDim.x + threadIdx.x;
    if (idx >= MN) return;
    float s = 0.f;
    for (int i = 0; i < S; i++) s += part[(size_t)i * MN + idx];
    s += bias[idx % N];
    if (relu) s = fmaxf(s, 0.f);
    out[idx] = s;
}

// ---------------- fp32 SGEMM (small fc layers) ----------------
__global__ void __launch_bounds__(256, 2)
sgemm_nt(const float* __restrict__ A, const float* __restrict__ B,
         float* __restrict__ C, int M, int N, int K, int kSlice)
{
    constexpr int BM = 128, BN = 128, BK = 8;
    __shared__ float As[BK][BM];
    __shared__ float Bs[BK][BN];
    const int tid = threadIdx.x;
    const int mBase = blockIdx.y * BM;
    const int nBase = blockIdx.x * BN;
    const int z = blockIdx.z;
    const int kBeg = z * kSlice;
    const int kEnd = kBeg + kSlice;
    const int lr = tid >> 1;
    const int lc = (tid & 1) * 4;
    const int tr = (tid >> 4) * 8;
    const int tc = (tid & 15) * 8;
    float acc[8][8];
#pragma unroll
    for (int i = 0; i < 8; i++)
#pragma unroll
        for (int j = 0; j < 8; j++) acc[i][j] = 0.f;
    const float* Aptr = A + (size_t)(mBase + lr) * K;
    const bool bvalid = (nBase + lr) < N;
    const float* Bptr = B + (bvalid ? (size_t)(nBase + lr) * K : 0);
    for (int k0 = kBeg; k0 < kEnd; k0 += BK) {
        float4 a4 = *reinterpret_cast<const float4*>(Aptr + k0 + lc);
        float4 b4 = make_float4(0.f, 0.f, 0.f, 0.f);
        if (bvalid) b4 = *reinterpret_cast<const float4*>(Bptr + k0 + lc);
        As[lc + 0][lr] = a4.x; As[lc + 1][lr] = a4.y;
        As[lc + 2][lr] = a4.z; As[lc + 3][lr] = a4.w;
        Bs[lc + 0][lr] = b4.x; Bs[lc + 1][lr] = b4.y;
        Bs[lc + 2][lr] = b4.z; Bs[lc + 3][lr] = b4.w;
        __syncthreads();
#pragma unroll
        for (int kk = 0; kk < BK; kk++) {
            float rm[8], rn[8];
#pragma unroll
            for (int i = 0; i < 8; i++) rm[i] = As[kk][tr + i];
#pragma unroll
            for (int j = 0; j < 8; j++) rn[j] = Bs[kk][tc + j];
#pragma unroll
            for (int i = 0; i < 8; i++)
#pragma unroll
                for (int j = 0; j < 8; j++) acc[i][j] = fmaf(rm[i], rn[j], acc[i][j]);
        }
        __syncthreads();
    }
    float* Cp = C + (size_t)z * M * N;
#pragma unroll
    for (int i = 0; i < 8; i++) {
        const size_t rowOff = (size_t)(mBase + tr + i) * N;
#pragma unroll
        for (int j = 0; j < 8; j++) {
            int col = nBase + tc + j;
            if (col < N) Cp[rowOff + col] = acc[i][j];
        }
    }
}

__global__ void fc3_kernel(const float* __restrict__ x, const float* __restrict__ W,
                           const float* __restrict__ b, float* __restrict__ out)
{
    int idx = blockIdx.x * blockDim.x + threadIdx.x;
    if (idx >= B_ * C3_) return;
    int m = idx / C3_;
    int n = idx - m * C3_;
    const float* xr = x + m * C2_;
    const float* wr = W + n * C2_;
    float s = 0.f;
#pragma unroll 4
    for (int k = 0; k < C2_; k++) s = fmaf(xr[k], wr[k], s);
    out[idx] = s + b[n];
}

// ---------------- launch ----------------
extern "C" void kernel_launch(void* const* d_in, const int* in_sizes, int n_in,
                              void* d_out_v, int out_size)
{
    const float* x     = (const float*)d_in[0];
    const float* W_ih0 = (const float*)d_in[1];
    const float* b_ih0 = (const float*)d_in[2];
    const float* b_hh0 = (const float*)d_in[3];
    const float* W_ih1 = (const float*)d_in[4];
    const float* b_ih1 = (const float*)d_in[5];
    const float* b_hh1 = (const float*)d_in[6];
    const float* fc1_w = (const float*)d_in[7];
    const float* fc1_b = (const float*)d_in[8];
    const float* fc2_w = (const float*)d_in[9];
    const float* fc2_b = (const float*)d_in[10];
    const float* fc3_w = (const float*)d_in[11];
    const float* fc3_b = (const float*)d_in[12];
    const float* fc4_w = (const float*)d_in[13];
    const float* fc4_b = (const float*)d_in[14];
    const float* fc5_w = (const float*)d_in[15];
    const float* fc5_b = (const float*)d_in[16];
    float* d_out = (float*)d_out_v;

    cudaFuncSetAttribute(hs_gemm, cudaFuncAttributeMaxDynamicSharedMemorySize, HS_SMEM_GATE);

    float *wsel0, *wsel1, *bsel0, *bsel1, *h0, *part, *c1, *c2, *r;
    cudaGetSymbolAddress((void**)&wsel0, g_wsel0);
    cudaGetSymbolAddress((void**)&wsel1, g_wsel1);
    cudaGetSymbolAddress((void**)&bsel0, g_bsel0);
    cudaGetSymbolAddress((void**)&bsel1, g_bsel1);
    cudaGetSymbolAddress((void**)&h0,    g_h0);
    cudaGetSymbolAddress((void**)&part,  g_part);
    cudaGetSymbolAddress((void**)&c1,    g_c1);
    cudaGetSymbolAddress((void**)&c2,    g_c2);
    cudaGetSymbolAddress((void**)&r,     g_r);

    // pack gate weights (fp32, skip forget gate)
    make_wsel<<<(G3 * D_ + 255) / 256, 256>>>(W_ih0, b_ih0, b_hh0, wsel0, bsel0, D_);
    make_wsel<<<(G3 * H_ + 255) / 256, 256>>>(W_ih1, b_ih1, b_hh1, wsel1, bsel1, H_);

    // LSTM layer 0 (gate mode): h0 = lstm(x @ Wsel0^T + bsel0)
    hs_gemm<<<dim3(2, BT / 128, 1), 512, HS_SMEM_GATE>>>(
        x, wsel0, h0, bsel0, BT, H_, D_, D_, 1);

    // LSTM layer 1 (gate mode): out_total = lstm(h0 @ Wsel1^T + bsel1) -> d_out
    hs_gemm<<<dim3(2, BT / 128, 1), 512, HS_SMEM_GATE>>>(
        h0, wsel1, d_out + OUT_TOTAL_OFF, bsel1, BT, H_, H_, H_, 1);

    const float* flat = d_out + OUT_TOTAL_OFF;  // [512, 51200] fp32

    // fc1 (split-K=16) + relu
    hs_gemm<<<dim3(C1_ / 128, B_ / 128, 16), 512, HS_OPER>>>(
        flat, fc1_w, part, nullptr, B_, C1_, HT, HT / 16, 0);
    reduce_bias_act<<<(B_ * C1_ + 255) / 256, 256>>>(part, 16, B_ * C1_, C1_, fc1_b, c1, 1);

    // fc2 (fp32 path) + relu
    sgemm_nt<<<dim3(C2_ / 128, B_ / 128, 4), 256>>>(c1, fc2_w, part, B_, C2_, C1_, C1_ / 4);
    reduce_bias_act<<<(B_ * C2_ + 255) / 256, 256>>>(part, 4, B_ * C2_, C2_, fc2_b, c2, 1);

    // fc3 -> class output
    fc3_kernel<<<(B_ * C3_ + 255) / 256, 256>>>(c2, fc3_w, fc3_b, d_out + OUT_CLASS_OFF);

    // fc4 (split-K=16) + relu
    hs_gemm<<<dim3(R1_ / 128, B_ / 128, 16), 512, HS_OPER>>>(
        flat, fc4_w, part, nullptr, B_, R1_, HT, HT / 16, 0);
    reduce_bias_act<<<(B_ * R1_ + 255) / 256, 256>>>(part, 16, B_ * R1_, R1_, fc4_b, r, 1);

    // fc5 (fp32 path, N=200 ragged) -> regression output
    sgemm_nt<<<dim3((T_ + 127) / 128, B_ / 128, 4), 256>>>(r, fc5_w, part, B_, T_, R1_, R1_ / 4);
    reduce_bias_act<<<(B_ * T_ + 255) / 256, 256>>>(part, 4, B_ * T_, T_, fc5_b,
                                                    d_out + OUT_REG_OFF, 0);
}

// round 12
// speedup vs baseline: 1.8893x; 1.2085x over previous
#include <cuda_runtime.h>
#include <cuda_fp16.h>
#include <math.h>
#include <stdint.h>

// ---------------- problem constants ----------------
constexpr int B_  = 512;
constexpr int T_  = 200;
constexpr int D_  = 64;
constexpr int H_  = 256;
constexpr int BT  = B_ * T_;        // 102400 rows
constexpr int HT  = H_ * T_;        // 51200 flat dim
constexpr int C1_ = 1024;
constexpr int C2_ = 256;
constexpr int C3_ = 10;
constexpr int R1_ = 1024;
constexpr int G3  = 768;            // packed gates i,g,o (forget gate dead, c0=0)

constexpr size_t OUT_TOTAL_OFF = 0;
constexpr size_t OUT_CLASS_OFF = (size_t)BT * H_;
constexpr size_t OUT_REG_OFF   = OUT_CLASS_OFF + (size_t)B_ * C3_;

// ---------------- device scratch ----------------
__device__ float g_wsel0[G3 * D_];          // packed i,g,o rows fp32
__device__ float g_wsel1[G3 * H_];
__device__ float g_bsel0[G3], g_bsel1[G3];
__device__ float g_h0[(size_t)BT * H_];     // 105 MB fp32
__device__ float g_part[16 * 512 * 1024];   // split-K partials
__device__ float g_c1[B_ * C1_];
__device__ float g_c2[B_ * C2_];
__device__ float g_r [B_ * R1_];

// ---------------- PTX helpers (sm_80-compatible only) ----------------
__device__ __forceinline__ uint32_t smem_u32(const void* p) {
    uint32_t a;
    asm("{ .reg .u64 t; cvta.to.shared.u64 t, %1; cvt.u32.u64 %0, t; }" : "=r"(a) : "l"(p));
    return a;
}
__device__ __forceinline__ void ldsm_x4(uint32_t* r, uint32_t addr) {
    asm volatile("ldmatrix.sync.aligned.m8n8.x4.shared.b16 {%0,%1,%2,%3}, [%4];"
                 : "=r"(r[0]), "=r"(r[1]), "=r"(r[2]), "=r"(r[3]) : "r"(addr));
}
__device__ __forceinline__ void mma_f16(float* c, const uint32_t* a, const uint32_t* b) {
    asm volatile("mma.sync.aligned.m16n8k16.row.col.f32.f16.f16.f32 "
                 "{%0,%1,%2,%3}, {%4,%5,%6,%7}, {%8,%9}, {%0,%1,%2,%3};"
                 : "+f"(c[0]), "+f"(c[1]), "+f"(c[2]), "+f"(c[3])
                 : "r"(a[0]), "r"(a[1]), "r"(a[2]), "r"(a[3]), "r"(b[0]), "r"(b[1]));
}
__device__ __forceinline__ uint32_t pack_h2(float a, float b) {
    __half2 t = __floats2half2_rn(a, b);
    return *reinterpret_cast<uint32_t*>(&t);
}
__device__ __forceinline__ float sigm(float x) { return 1.f / (1.f + expf(-x)); }

// ---------------- single-pass fp16 HMMA GEMM (fp32 in, fp32 out) ----------------
// C ~= fp16(A) * fp16(B)^T  (both rounded to fp16; rel err ~2^-12 incoherent
// over K, measured ~2.3e-4 total vs 1e-3 threshold).
// Standard mode: C[z][M,N] partial over k-slice z.
// Gate mode: g in {i,g,o}: acc_g = A * Wsel[g*256+n,:]^T + bias; h via SMEM stash.
// Tile 128x128x64, 512 threads, warp grid 4x4, warp tile 32x32.
// Single operand buffer, two syncs per chunk (R6/R10 structure — best measured).
constexpr int HS_ROWB  = 144;               // 64 fp16 + 8 pad, bytes
constexpr int HS_TILE  = 128 * HS_ROWB;     // 18432
constexpr int HS_OPER  = 2 * HS_TILE;       // 36864 (A | B)
constexpr int HS_STASH = 128 * 132 * 4;     // 67584 (128x128 fp32, pad)
constexpr int HS_SMEM_GATE = HS_OPER + HS_STASH;   // 104448

__global__ void __launch_bounds__(512, 1)
hs_gemm(const float* __restrict__ A, const float* __restrict__ Bw,
        float* __restrict__ C, const float* __restrict__ bias,
        int M, int N, int K, int kSlice, int gateMode)
{
    extern __shared__ __align__(128) char smem[];
    char* pA = smem;
    char* pB = smem + HS_TILE;
    float* stash = reinterpret_cast<float*>(smem + HS_OPER);
    const uint32_t sA = smem_u32(pA);
    const uint32_t sB = sA + HS_TILE;

    const int tid  = threadIdx.x;
    const int lane = tid & 31;
    const int warp = tid >> 5;
    const int wm   = warp >> 2;              // 0..3
    const int wn   = warp & 3;               // 0..3
    const int mBase = blockIdx.y * 128;
    const int nBase = blockIdx.x * 128;
    const int z     = gateMode ? 0 : blockIdx.z;
    const int kBeg  = z * kSlice;
    const int NC    = kSlice >> 6;

    const int aRow  = (lane & 7) + ((lane >> 3) & 1) * 8;
    const int aCol  = (lane >> 4) * 8;
    const int bRow4 = ((lane >> 4) & 1) * 8 + (lane & 7);   // paired-x4 B row
    const int bColH = ((lane >> 3) & 1) * 8;                // k-half select

    // loader: 2048 float4 per operand tile, 4 per thread
    int lr[4], lc4[4];
#pragma unroll
    for (int t = 0; t < 4; t++) {
        int idx = tid + t * 512;
        lr[t]  = idx >> 4;        // 0..127
        lc4[t] = idx & 15;        // float4 unit within 64-col row
    }

    const int nGates = gateMode ? 3 : 1;

    for (int g = 0; g < nGates; g++) {
        const int rowOff = gateMode ? (g * 256 + nBase) : nBase;

        float acc[2][4][4];
#pragma unroll
        for (int mi = 0; mi < 2; mi++)
#pragma unroll
            for (int ni = 0; ni < 4; ni++)
#pragma unroll
                for (int q = 0; q < 4; q++) acc[mi][ni][q] = 0.f;

        float4 aR[4], bR[4];

        auto ldg_chunk = [&](int c) {
            int kk = kBeg + c * 64;
#pragma unroll
            for (int t = 0; t < 4; t++) {
                aR[t] = *reinterpret_cast<const float4*>(A  + (size_t)(mBase + lr[t]) * K + kk + lc4[t] * 4);
                bR[t] = *reinterpret_cast<const float4*>(Bw + (size_t)(rowOff + lr[t]) * K + kk + lc4[t] * 4);
            }
        };
        auto sts_cvt = [&]() {
#pragma unroll
            for (int t = 0; t < 4; t++) {
                int off = lr[t] * HS_ROWB + lc4[t] * 8;
                float4 v = aR[t];
                *reinterpret_cast<uint2*>(pA + off) =
                    make_uint2(pack_h2(v.x, v.y), pack_h2(v.z, v.w));
                v = bR[t];
                *reinterpret_cast<uint2*>(pB + off) =
                    make_uint2(pack_h2(v.x, v.y), pack_h2(v.z, v.w));
            }
        };

        ldg_chunk(0);
        for (int c = 0; c < NC; c++) {
            __syncthreads();                 // prior MMA done before overwrite
            sts_cvt();
            __syncthreads();
            if (c + 1 < NC) ldg_chunk(c + 1);

#pragma unroll
            for (int ks = 0; ks < 4; ks++) {
                uint32_t ah[2][4], bh[2][4];
#pragma unroll
                for (int mi = 0; mi < 2; mi++) {
                    uint32_t ro = (wm * 32 + mi * 16 + aRow) * HS_ROWB + (ks * 16 + aCol) * 2;
                    ldsm_x4(ah[mi], sA + ro);
                }
#pragma unroll
                for (int p = 0; p < 2; p++) {
                    uint32_t ro = (wn * 32 + p * 16 + bRow4) * HS_ROWB + (ks * 16 + bColH) * 2;
                    ldsm_x4(bh[p], sB + ro);
                }
#pragma unroll
                for (int mi = 0; mi < 2; mi++)
#pragma unroll
                    for (int ni = 0; ni < 4; ni++)
                        mma_f16(acc[mi][ni], ah[mi], &bh[ni >> 1][(ni & 1) * 2]);
            }
        }

        // ---- epilogue ----
        if (!gateMode) {
            float* Cp = C + (size_t)z * M * N;
#pragma unroll
            for (int mi = 0; mi < 2; mi++) {
                int r0 = mBase + wm * 32 + mi * 16 + (lane >> 2);
#pragma unroll
                for (int ni = 0; ni < 4; ni++) {
                    int col = nBase + wn * 32 + ni * 8 + (lane & 3) * 2;
                    *reinterpret_cast<float2*>(&Cp[(size_t)r0 * N + col]) =
                        make_float2(acc[mi][ni][0], acc[mi][ni][1]);
                    *reinterpret_cast<float2*>(&Cp[(size_t)(r0 + 8) * N + col]) =
                        make_float2(acc[mi][ni][2], acc[mi][ni][3]);
                }
            }
        } else {
#pragma unroll
            for (int mi = 0; mi < 2; mi++)
#pragma unroll
                for (int ni = 0; ni < 4; ni++)
#pragma unroll
                    for (int q = 0; q < 4; q++) {
                        int rl = wm * 32 + mi * 16 + (lane >> 2) + ((q >= 2) ? 8 : 0);
                        int cl = wn * 32 + ni * 8 + (lane & 3) * 2 + (q & 1);
                        float v = acc[mi][ni][q] + bias[rowOff + cl];
                        int si = rl * 132 + cl;
                        if (g == 0)      stash[si] = sigm(v);
                        else if (g == 1) stash[si] *= tanhf(v);
                        else {
                            float h = sigm(v) * tanhf(stash[si]);
                            C[(size_t)(mBase + rl) * H_ + nBase + cl] = h;
                        }
                    }
        }
    }
}

// ---------------- small kernels ----------------
__global__ void make_wsel(const float* __restrict__ W, const float* __restrict__ bih,
                          const float* __restrict__ bhh, float* __restrict__ Wsel,
                          float* __restrict__ bsel, int Kd)
{
    int idx = blockIdx.x * blockDim.x + threadIdx.x;
    int total = G3 * Kd;
    if (idx < total) {
        int j = idx / Kd;
        int c = idx - j * Kd;
        int src = j + ((j >= 256) ? 256 : 0);
        Wsel[idx] = W[src * Kd + c];
    }
    if (idx < G3) {
        int src = idx + ((idx >= 256) ? 256 : 0);
        bsel[idx] = bih[src] + bhh[src];
    }
}

__global__ void reduce_bias_act(const float* __restrict__ part, int S, int MN, int N,
                                const float* __restrict__ bias, float* __restrict__ out, int relu)
{
    int idx = blockIdx.x * blockDim.x + threadIdx.x;
    if (idx >= MN) return;
    float s = 0.f;
    for (int i = 0; i < S; i++) s += part[(size_t)i * MN + idx];
    s += bias[idx % N];
    if (relu) s = fmaxf(s, 0.f);
    out[idx] = s;
}

// ---------------- fp32 SGEMM (small fc layers) ----------------
__global__ void __launch_bounds__(256, 2)
sgemm_nt(const float* __restrict__ A, const float* __restrict__ B,
         float* __restrict__ C, int M, int N, int K, int kSlice)
{
    constexpr int BM = 128, BN = 128, BK = 8;
    __shared__ float As[BK][BM];
    __shared__ float Bs[BK][BN];
    const int tid = threadIdx.x;
    const int mBase = blockIdx.y * BM;
    const int nBase = blockIdx.x * BN;
    const int z = blockIdx.z;
    const int kBeg = z * kSlice;
    const int kEnd = kBeg + kSlice;
    const int lr = tid >> 1;
    const int lc = (tid & 1) * 4;
    const int tr = (tid >> 4) * 8;
    const int tc = (tid & 15) * 8;
    float acc[8][8];
#pragma unroll
    for (int i = 0; i < 8; i++)
#pragma unroll
        for (int j = 0; j < 8; j++) acc[i][j] = 0.f;
    const float* Aptr = A + (size_t)(mBase + lr) * K;
    const bool bvalid = (nBase + lr) < N;
    const float* Bptr = B + (bvalid ? (size_t)(nBase + lr) * K : 0);
    for (int k0 = kBeg; k0 < kEnd; k0 += BK) {
        float4 a4 = *reinterpret_cast<const float4*>(Aptr + k0 + lc);
        float4 b4 = make_float4(0.f, 0.f, 0.f, 0.f);
        if (bvalid) b4 = *reinterpret_cast<const float4*>(Bptr + k0 + lc);
        As[lc + 0][lr] = a4.x; As[lc + 1][lr] = a4.y;
        As[lc + 2][lr] = a4.z; As[lc + 3][lr] = a4.w;
        Bs[lc + 0][lr] = b4.x; Bs[lc + 1][lr] = b4.y;
        Bs[lc + 2][lr] = b4.z; Bs[lc + 3][lr] = b4.w;
        __syncthreads();
#pragma unroll
        for (int kk = 0; kk < BK; kk++) {
            float rm[8], rn[8];
#pragma unroll
            for (int i = 0; i < 8; i++) rm[i] = As[kk][tr + i];
#pragma unroll
            for (int j = 0; j < 8; j++) rn[j] = Bs[kk][tc + j];
#pragma unroll
            for (int i = 0; i < 8; i++)
#pragma unroll
                for (int j = 0; j < 8; j++) acc[i][j] = fmaf(rm[i], rn[j], acc[i][j]);
        }
        __syncthreads();
    }
    float* Cp = C + (size_t)z * M * N;
#pragma unroll
    for (int i = 0; i < 8; i++) {
        const size_t rowOff = (size_t)(mBase + tr + i) * N;
#pragma unroll
        for (int j = 0; j < 8; j++) {
            int col = nBase + tc + j;
            if (col < N) Cp[rowOff + col] = acc[i][j];
        }
    }
}

__global__ void fc3_kernel(const float* __restrict__ x, const float* __restrict__ W,
                           const float* __restrict__ b, float* __restrict__ out)
{
    int idx = blockIdx.x * blockDim.x + threadIdx.x;
    if (idx >= B_ * C3_) return;
    int m = idx / C3_;
    int n = idx - m * C3_;
    const float* xr = x + m * C2_;
    const float* wr = W + n * C2_;
    float s = 0.f;
#pragma unroll 4
    for (int k = 0; k < C2_; k++) s = fmaf(xr[k], wr[k], s);
    out[idx] = s + b[n];
}

// ---------------- launch ----------------
extern "C" void kernel_launch(void* const* d_in, const int* in_sizes, int n_in,
                              void* d_out_v, int out_size)
{
    const float* x     = (const float*)d_in[0];
    const float* W_ih0 = (const float*)d_in[1];
    const float* b_ih0 = (const float*)d_in[2];
    const float* b_hh0 = (const float*)d_in[3];
    const float* W_ih1 = (const float*)d_in[4];
    const float* b_ih1 = (const float*)d_in[5];
    const float* b_hh1 = (const float*)d_in[6];
    const float* fc1_w = (const float*)d_in[7];
    const float* fc1_b = (const float*)d_in[8];
    const float* fc2_w = (const float*)d_in[9];
    const float* fc2_b = (const float*)d_in[10];
    const float* fc3_w = (const float*)d_in[11];
    const float* fc3_b = (const float*)d_in[12];
    const float* fc4_w = (const float*)d_in[13];
    const float* fc4_b = (const float*)d_in[14];
    const float* fc5_w = (const float*)d_in[15];
    const float* fc5_b = (const float*)d_in[16];
    float* d_out = (float*)d_out_v;

    cudaFuncSetAttribute(hs_gemm, cudaFuncAttributeMaxDynamicSharedMemorySize, HS_SMEM_GATE);

    float *wsel0, *wsel1, *bsel0, *bsel1, *h0, *part, *c1, *c2, *r;
    cudaGetSymbolAddress((void**)&wsel0, g_wsel0);
    cudaGetSymbolAddress((void**)&wsel1, g_wsel1);
    cudaGetSymbolAddress((void**)&bsel0, g_bsel0);
    cudaGetSymbolAddress((void**)&bsel1, g_bsel1);
    cudaGetSymbolAddress((void**)&h0,    g_h0);
    cudaGetSymbolAddress((void**)&part,  g_part);
    cudaGetSymbolAddress((void**)&c1,    g_c1);
    cudaGetSymbolAddress((void**)&c2,    g_c2);
    cudaGetSymbolAddress((void**)&r,     g_r);

    // pack gate weights (fp32, skip forget gate)
    make_wsel<<<(G3 * D_ + 255) / 256, 256>>>(W_ih0, b_ih0, b_hh0, wsel0, bsel0, D_);
    make_wsel<<<(G3 * H_ + 255) / 256, 256>>>(W_ih1, b_ih1, b_hh1, wsel1, bsel1, H_);

    // LSTM layer 0 (gate mode): h0 = lstm(x @ Wsel0^T + bsel0)
    hs_gemm<<<dim3(2, BT / 128, 1), 512, HS_SMEM_GATE>>>(
        x, wsel0, h0, bsel0, BT, H_, D_, D_, 1);

    // LSTM layer 1 (gate mode): out_total = lstm(h0 @ Wsel1^T + bsel1) -> d_out
    hs_gemm<<<dim3(2, BT / 128, 1), 512, HS_SMEM_GATE>>>(
        h0, wsel1, d_out + OUT_TOTAL_OFF, bsel1, BT, H_, H_, H_, 1);

    const float* flat = d_out + OUT_TOTAL_OFF;  // [512, 51200] fp32

    // fc1 (split-K=16) + relu
    hs_gemm<<<dim3(C1_ / 128, B_ / 128, 16), 512, HS_OPER>>>(
        flat, fc1_w, part, nullptr, B_, C1_, HT, HT / 16, 0);
    reduce_bias_act<<<(B_ * C1_ + 255) / 256, 256>>>(part, 16, B_ * C1_, C1_, fc1_b, c1, 1);

    // fc2 (fp32 path) + relu
    sgemm_nt<<<dim3(C2_ / 128, B_ / 128, 4), 256>>>(c1, fc2_w, part, B_, C2_, C1_, C1_ / 4);
    reduce_bias_act<<<(B_ * C2_ + 255) / 256, 256>>>(part, 4, B_ * C2_, C2_, fc2_b, c2, 1);

    // fc3 -> class output
    fc3_kernel<<<(B_ * C3_ + 255) / 256, 256>>>(c2, fc3_w, fc3_b, d_out + OUT_CLASS_OFF);

    // fc4 (split-K=16) + relu
    hs_gemm<<<dim3(R1_ / 128, B_ / 128, 16), 512, HS_OPER>>>(
        flat, fc4_w, part, nullptr, B_, R1_, HT, HT / 16, 0);
    reduce_bias_act<<<(B_ * R1_ + 255) / 256, 256>>>(part, 16, B_ * R1_, R1_, fc4_b, r, 1);

    // fc5 (fp32 path, N=200 ragged) -> regression output
    sgemm_nt<<<dim3((T_ + 127) / 128, B_ / 128, 4), 256>>>(r, fc5_w, part, B_, T_, R1_, R1_ / 4);
    reduce_bias_act<<<(B_ * T_ + 255) / 256, 256>>>(part, 4, B_ * T_, T_, fc5_b,
                                                    d_out + OUT_REG_OFF, 0);
}

// round 13
// speedup vs baseline: 1.9249x; 1.0189x over previous
#include <cuda_runtime.h>
#include <cuda_fp16.h>
#include <math.h>
#include <stdint.h>

// ---------------- problem constants ----------------
constexpr int B_  = 512;
constexpr int T_  = 200;
constexpr int D_  = 64;
constexpr int H_  = 256;
constexpr int BT  = B_ * T_;        // 102400 rows
constexpr int HT  = H_ * T_;        // 51200 flat dim
constexpr int C1_ = 1024;
constexpr int C2_ = 256;
constexpr int C3_ = 10;
constexpr int R1_ = 1024;
constexpr int G3  = 768;            // packed gates i,g,o (forget gate dead, c0=0)

constexpr size_t OUT_TOTAL_OFF = 0;
constexpr size_t OUT_CLASS_OFF = (size_t)BT * H_;
constexpr size_t OUT_REG_OFF   = OUT_CLASS_OFF + (size_t)B_ * C3_;

// ---------------- device scratch ----------------
__device__ __half g_w0h[G3 * D_];           // packed i,g,o rows fp16
__device__ __half g_w1h[G3 * H_];
__device__ float  g_bsel0[G3], g_bsel1[G3];
__device__ __half g_xh [(size_t)BT * D_];   // fp16 input
__device__ __half g_h0h[(size_t)BT * H_];   // fp16 h0
__device__ __half g_fh [(size_t)BT * H_];   // fp16 flat (out_total)
__device__ __half g_f1h[(size_t)C1_ * HT];  // fp16 fc1 weights
__device__ __half g_f4h[(size_t)R1_ * HT];  // fp16 fc4 weights
__device__ float  g_part[16 * 512 * 1024];  // split-K partials
__device__ float  g_c1[B_ * C1_];
__device__ float  g_c2[B_ * C2_];
__device__ float  g_r [B_ * R1_];

// ---------------- PTX helpers (sm_80-compatible only) ----------------
__device__ __forceinline__ uint32_t smem_u32(const void* p) {
    uint32_t a;
    asm("{ .reg .u64 t; cvta.to.shared.u64 t, %1; cvt.u32.u64 %0, t; }" : "=r"(a) : "l"(p));
    return a;
}
__device__ __forceinline__ void cp_async16(uint32_t dst, const void* src) {
    asm volatile("cp.async.cg.shared.global [%0], [%1], 16;" :: "r"(dst), "l"(src));
}
#define CP_COMMIT() asm volatile("cp.async.commit_group;" ::: "memory")
template <int N>
__device__ __forceinline__ void cp_wait() {
    asm volatile("cp.async.wait_group %0;" :: "n"(N) : "memory");
}
__device__ __forceinline__ void ldsm_x4(uint32_t* r, uint32_t addr) {
    asm volatile("ldmatrix.sync.aligned.m8n8.x4.shared.b16 {%0,%1,%2,%3}, [%4];"
                 : "=r"(r[0]), "=r"(r[1]), "=r"(r[2]), "=r"(r[3]) : "r"(addr));
}
__device__ __forceinline__ void mma_f16(float* c, const uint32_t* a, const uint32_t* b) {
    asm volatile("mma.sync.aligned.m16n8k16.row.col.f32.f16.f16.f32 "
                 "{%0,%1,%2,%3}, {%4,%5,%6,%7}, {%8,%9}, {%0,%1,%2,%3};"
                 : "+f"(c[0]), "+f"(c[1]), "+f"(c[2]), "+f"(c[3])
                 : "r"(a[0]), "r"(a[1]), "r"(a[2]), "r"(a[3]), "r"(b[0]), "r"(b[1]));
}
__device__ __forceinline__ uint32_t pack_h2(float a, float b) {
    __half2 t = __floats2half2_rn(a, b);
    return *reinterpret_cast<uint32_t*>(&t);
}
__device__ __forceinline__ float sigm(float x) { return 1.f / (1.f + expf(-x)); }

// ---------------- single-pass fp16 HMMA GEMM (fp16 in) ----------------
// Standard mode: C[z][M,N] partial = A[M,K] * B[N,K]^T over k-slice z (fp32 out).
// Gate mode: g in {i,g,o}: acc_g = A * Wsel[g*256+n,:]^T + bias; h composed in
//            REGISTER stash; writes fp16 outH plus optional fp32 C.
// Tile 128x128x64, 512 threads, warp grid 4x4, warp tile 32x32.
// 3-stage cp.async pipeline; operands pre-converted to fp16 (no in-loop cvt).
constexpr int HS_ROWB  = 144;               // 64 fp16 + 8 pad, bytes
constexpr int HS_TILE  = 128 * HS_ROWB;     // 18432
constexpr int HS_STAGE = 2 * HS_TILE;       // 36864 (A | B)
constexpr int HS_SMEM  = 3 * HS_STAGE;      // 110592

__global__ void __launch_bounds__(512, 1)
hs_gemm(const __half* __restrict__ A, const __half* __restrict__ Bw,
        float* __restrict__ C, const float* __restrict__ bias,
        __half* __restrict__ outH,
        int M, int N, int K, int kSlice, int gateMode)
{
    extern __shared__ __align__(128) char smem[];
    const uint32_t sBase = smem_u32(smem);

    const int tid  = threadIdx.x;
    const int lane = tid & 31;
    const int warp = tid >> 5;
    const int wm   = warp >> 2;              // 0..3
    const int wn   = warp & 3;               // 0..3
    const int mBase = blockIdx.y * 128;
    const int nBase = blockIdx.x * 128;
    const int z     = gateMode ? 0 : blockIdx.z;
    const int kBeg  = z * kSlice;
    const int NC    = kSlice >> 6;

    const int aRow  = (lane & 7) + ((lane >> 3) & 1) * 8;
    const int aCol  = (lane >> 4) * 8;
    const int bRow4 = ((lane >> 4) & 1) * 8 + (lane & 7);   // paired-x4 B row
    const int bColH = ((lane >> 3) & 1) * 8;                // k-half select

    // cp.async loader: 1024 x 16B chunks per tile, 2 per thread per tile
    const int lrow0 = tid >> 3;              // 0..63
    const int lrow1 = lrow0 + 64;            // 64..127
    const int lc8   = tid & 7;               // 16B unit in 128B row

    const int nGates = gateMode ? 3 : 1;
    float stash[2][4][4];                    // sigm(i), then sigm(i)*tanh(g)

    for (int g = 0; g < nGates; g++) {
        const int rowOff = gateMode ? (g * 256 + nBase) : nBase;

        float acc[2][4][4];
#pragma unroll
        for (int mi = 0; mi < 2; mi++)
#pragma unroll
            for (int ni = 0; ni < 4; ni++)
#pragma unroll
                for (int q = 0; q < 4; q++) acc[mi][ni][q] = 0.f;

        auto prefetch = [&](int c) {
            if (c < NC) {
                int kk = kBeg + c * 64;
                uint32_t st = sBase + (c % 3) * HS_STAGE;
                cp_async16(st + lrow0 * HS_ROWB + lc8 * 16,
                           A + (size_t)(mBase + lrow0) * K + kk + lc8 * 8);
                cp_async16(st + lrow1 * HS_ROWB + lc8 * 16,
                           A + (size_t)(mBase + lrow1) * K + kk + lc8 * 8);
                cp_async16(st + HS_TILE + lrow0 * HS_ROWB + lc8 * 16,
                           Bw + (size_t)(rowOff + lrow0) * K + kk + lc8 * 8);
                cp_async16(st + HS_TILE + lrow1 * HS_ROWB + lc8 * 16,
                           Bw + (size_t)(rowOff + lrow1) * K + kk + lc8 * 8);
            }
            CP_COMMIT();                      // unconditional: fixed group count
        };

        prefetch(0); prefetch(1); prefetch(2);

        for (int c = 0; c < NC; c++) {
            cp_wait<2>();                    // group c complete (3 in flight)
            __syncthreads();

            uint32_t sA = sBase + (c % 3) * HS_STAGE;
            uint32_t sB = sA + HS_TILE;
#pragma unroll
            for (int ks = 0; ks < 4; ks++) {
                uint32_t ah[2][4], bh[2][4];
#pragma unroll
                for (int mi = 0; mi < 2; mi++) {
                    uint32_t ro = (wm * 32 + mi * 16 + aRow) * HS_ROWB + (ks * 16 + aCol) * 2;
                    ldsm_x4(ah[mi], sA + ro);
                }
#pragma unroll
                for (int p = 0; p < 2; p++) {
                    uint32_t ro = (wn * 32 + p * 16 + bRow4) * HS_ROWB + (ks * 16 + bColH) * 2;
                    ldsm_x4(bh[p], sB + ro);
                }
#pragma unroll
                for (int mi = 0; mi < 2; mi++)
#pragma unroll
                    for (int ni = 0; ni < 4; ni++)
                        mma_f16(acc[mi][ni], ah[mi], &bh[ni >> 1][(ni & 1) * 2]);
            }
            __syncthreads();                 // stage drained before refill
            prefetch(c + 3);
        }

        // ---- epilogue ----
        if (!gateMode) {
            float* Cp = C + (size_t)z * M * N;
#pragma unroll
            for (int mi = 0; mi < 2; mi++) {
                int r0 = mBase + wm * 32 + mi * 16 + (lane >> 2);
#pragma unroll
                for (int ni = 0; ni < 4; ni++) {
                    int col = nBase + wn * 32 + ni * 8 + (lane & 3) * 2;
                    *reinterpret_cast<float2*>(&Cp[(size_t)r0 * N + col]) =
                        make_float2(acc[mi][ni][0], acc[mi][ni][1]);
                    *reinterpret_cast<float2*>(&Cp[(size_t)(r0 + 8) * N + col]) =
                        make_float2(acc[mi][ni][2], acc[mi][ni][3]);
                }
            }
        } else {
#pragma unroll
            for (int mi = 0; mi < 2; mi++)
#pragma unroll
                for (int ni = 0; ni < 4; ni++)
#pragma unroll
                    for (int q = 0; q < 4; q++) {
                        int rl = wm * 32 + mi * 16 + (lane >> 2) + ((q >= 2) ? 8 : 0);
                        int cl = wn * 32 + ni * 8 + (lane & 3) * 2 + (q & 1);
                        float v = acc[mi][ni][q] + bias[rowOff + cl];
                        if (g == 0)      stash[mi][ni][q] = sigm(v);
                        else if (g == 1) stash[mi][ni][q] *= tanhf(v);
                        else {
                            float h = sigm(v) * tanhf(stash[mi][ni][q]);
                            size_t o = (size_t)(mBase + rl) * H_ + nBase + cl;
                            if (C) C[o] = h;
                            outH[o] = __float2half(h);
                        }
                    }
        }
    }
}

// ---------------- prep kernels ----------------
// fp32 -> fp16, vectorized (4 elems/thread)
__global__ void cvt_f16(const float4* __restrict__ src, uint2* __restrict__ dst, int n4)
{
    int i = blockIdx.x * blockDim.x + threadIdx.x;
    if (i >= n4) return;
    float4 v = src[i];
    dst[i] = make_uint2(pack_h2(v.x, v.y), pack_h2(v.z, v.w));
}

// pack gate rows {i, g, o} of W_ih -> fp16; bsel = b_ih + b_hh
__global__ void make_wsel_f16(const float* __restrict__ W, const float* __restrict__ bih,
                              const float* __restrict__ bhh, __half* __restrict__ Wh,
                              float* __restrict__ bsel, int Kd)
{
    int idx = blockIdx.x * blockDim.x + threadIdx.x;
    int total = G3 * Kd;
    if (idx < total) {
        int j = idx / Kd;
        int c = idx - j * Kd;
        int src = j + ((j >= 256) ? 256 : 0);
        Wh[idx] = __float2half(W[src * Kd + c]);
    }
    if (idx < G3) {
        int src = idx + ((idx >= 256) ? 256 : 0);
        bsel[idx] = bih[src] + bhh[src];
    }
}

__global__ void reduce_bias_act(const float* __restrict__ part, int S, int MN, int N,
                                const float* __restrict__ bias, float* __restrict__ out, int relu)
{
    int idx = blockIdx.x * blockDim.x + threadIdx.x;
    if (idx >= MN) return;
    float s = 0.f;
    for (int i = 0; i < S; i++) s += part[(size_t)i * MN + idx];
    s += bias[idx % N];
    if (relu) s = fmaxf(s, 0.f);
    out[idx] = s;
}

// ---------------- fp32 SGEMM (small fc layers) ----------------
__global__ void __launch_bounds__(256, 2)
sgemm_nt(const float* __restrict__ A, const float* __restrict__ B,
         float* __restrict__ C, int M, int N, int K, int kSlice)
{
    constexpr int BM = 128, BN = 128, BK = 8;
    __shared__ float As[BK][BM];
    __shared__ float Bs[BK][BN];
    const int tid = threadIdx.x;
    const int mBase = blockIdx.y * BM;
    const int nBase = blockIdx.x * BN;
    const int z = blockIdx.z;
    const int kBeg = z * kSlice;
    const int kEnd = kBeg + kSlice;
    const int lr = tid >> 1;
    const int lc = (tid & 1) * 4;
    const int tr = (tid >> 4) * 8;
    const int tc = (tid & 15) * 8;
    float acc[8][8];
#pragma unroll
    for (int i = 0; i < 8; i++)
#pragma unroll
        for (int j = 0; j < 8; j++) acc[i][j] = 0.f;
    const float* Aptr = A + (size_t)(mBase + lr) * K;
    const bool bvalid = (nBase + lr) < N;
    const float* Bptr = B + (bvalid ? (size_t)(nBase + lr) * K : 0);
    for (int k0 = kBeg; k0 < kEnd; k0 += BK) {
        float4 a4 = *reinterpret_cast<const float4*>(Aptr + k0 + lc);
        float4 b4 = make_float4(0.f, 0.f, 0.f, 0.f);
        if (bvalid) b4 = *reinterpret_cast<const float4*>(Bptr + k0 + lc);
        As[lc + 0][lr] = a4.x; As[lc + 1][lr] = a4.y;
        As[lc + 2][lr] = a4.z; As[lc + 3][lr] = a4.w;
        Bs[lc + 0][lr] = b4.x; Bs[lc + 1][lr] = b4.y;
        Bs[lc + 2][lr] = b4.z; Bs[lc + 3][lr] = b4.w;
        __syncthreads();
#pragma unroll
        for (int kk = 0; kk < BK; kk++) {
            float rm[8], rn[8];
#pragma unroll
            for (int i = 0; i < 8; i++) rm[i] = As[kk][tr + i];
#pragma unroll
            for (int j = 0; j < 8; j++) rn[j] = Bs[kk][tc + j];
#pragma unroll
            for (int i = 0; i < 8; i++)
#pragma unroll
                for (int j = 0; j < 8; j++) acc[i][j] = fmaf(rm[i], rn[j], acc[i][j]);
        }
        __syncthreads();
    }
    float* Cp = C + (size_t)z * M * N;
#pragma unroll
    for (int i = 0; i < 8; i++) {
        const size_t rowOff = (size_t)(mBase + tr + i) * N;
#pragma unroll
        for (int j = 0; j < 8; j++) {
            int col = nBase + tc + j;
            if (col < N) Cp[rowOff + col] = acc[i][j];
        }
    }
}

__global__ void fc3_kernel(const float* __restrict__ x, const float* __restrict__ W,
                           const float* __restrict__ b, float* __restrict__ out)
{
    int idx = blockIdx.x * blockDim.x + threadIdx.x;
    if (idx >= B_ * C3_) return;
    int m = idx / C3_;
    int n = idx - m * C3_;
    const float* xr = x + m * C2_;
    const float* wr = W + n * C2_;
    float s = 0.f;
#pragma unroll 4
    for (int k = 0; k < C2_; k++) s = fmaf(xr[k], wr[k], s);
    out[idx] = s + b[n];
}

// ---------------- launch ----------------
extern "C" void kernel_launch(void* const* d_in, const int* in_sizes, int n_in,
                              void* d_out_v, int out_size)
{
    const float* x     = (const float*)d_in[0];
    const float* W_ih0 = (const float*)d_in[1];
    const float* b_ih0 = (const float*)d_in[2];
    const float* b_hh0 = (const float*)d_in[3];
    const float* W_ih1 = (const float*)d_in[4];
    const float* b_ih1 = (const float*)d_in[5];
    const float* b_hh1 = (const float*)d_in[6];
    const float* fc1_w = (const float*)d_in[7];
    const float* fc1_b = (const float*)d_in[8];
    const float* fc2_w = (const float*)d_in[9];
    const float* fc2_b = (const float*)d_in[10];
    const float* fc3_w = (const float*)d_in[11];
    const float* fc3_b = (const float*)d_in[12];
    const float* fc4_w = (const float*)d_in[13];
    const float* fc4_b = (const float*)d_in[14];
    const float* fc5_w = (const float*)d_in[15];
    const float* fc5_b = (const float*)d_in[16];
    float* d_out = (float*)d_out_v;

    cudaFuncSetAttribute(hs_gemm, cudaFuncAttributeMaxDynamicSharedMemorySize, HS_SMEM);

    __half *w0h, *w1h, *xh, *h0h, *fh, *f1h, *f4h;
    float *bsel0, *bsel1, *part, *c1, *c2, *r;
    cudaGetSymbolAddress((void**)&w0h, g_w0h);
    cudaGetSymbolAddress((void**)&w1h, g_w1h);
    cudaGetSymbolAddress((void**)&bsel0, g_bsel0);
    cudaGetSymbolAddress((void**)&bsel1, g_bsel1);
    cudaGetSymbolAddress((void**)&xh,  g_xh);
    cudaGetSymbolAddress((void**)&h0h, g_h0h);
    cudaGetSymbolAddress((void**)&fh,  g_fh);
    cudaGetSymbolAddress((void**)&f1h, g_f1h);
    cudaGetSymbolAddress((void**)&f4h, g_f4h);
    cudaGetSymbolAddress((void**)&part, g_part);
    cudaGetSymbolAddress((void**)&c1, g_c1);
    cudaGetSymbolAddress((void**)&c2, g_c2);
    cudaGetSymbolAddress((void**)&r,  g_r);

    // prep: pack gate weights fp16 + convert x / fc weights to fp16 (one-time)
    make_wsel_f16<<<(G3 * D_ + 255) / 256, 256>>>(W_ih0, b_ih0, b_hh0, w0h, bsel0, D_);
    make_wsel_f16<<<(G3 * H_ + 255) / 256, 256>>>(W_ih1, b_ih1, b_hh1, w1h, bsel1, H_);
    cvt_f16<<<(BT * D_ / 4 + 255) / 256, 256>>>((const float4*)x, (uint2*)xh, BT * D_ / 4);
    cvt_f16<<<(C1_ * HT / 4 + 255) / 256, 256>>>((const float4*)fc1_w, (uint2*)f1h, C1_ * HT / 4);
    cvt_f16<<<(R1_ * HT / 4 + 255) / 256, 256>>>((const float4*)fc4_w, (uint2*)f4h, R1_ * HT / 4);

    // LSTM layer 0 (gate mode): h0 fp16 = lstm(x @ Wsel0^T + bsel0)
    hs_gemm<<<dim3(2, BT / 128, 1), 512, HS_SMEM>>>(
        xh, w0h, nullptr, bsel0, h0h, BT, H_, D_, D_, 1);

    // LSTM layer 1 (gate mode): out_total fp32 -> d_out, flat fp16 -> fh
    hs_gemm<<<dim3(2, BT / 128, 1), 512, HS_SMEM>>>(
        h0h, w1h, d_out + OUT_TOTAL_OFF, bsel1, fh, BT, H_, H_, H_, 1);

    // fc1 (split-K=16) + relu
    hs_gemm<<<dim3(C1_ / 128, B_ / 128, 16), 512, HS_SMEM>>>(
        fh, f1h, part, nullptr, nullptr, B_, C1_, HT, HT / 16, 0);
    reduce_bias_act<<<(B_ * C1_ + 255) / 256, 256>>>(part, 16, B_ * C1_, C1_, fc1_b, c1, 1);

    // fc2 (fp32 path) + relu
    sgemm_nt<<<dim3(C2_ / 128, B_ / 128, 4), 256>>>(c1, fc2_w, part, B_, C2_, C1_, C1_ / 4);
    reduce_bias_act<<<(B_ * C2_ + 255) / 256, 256>>>(part, 4, B_ * C2_, C2_, fc2_b, c2, 1);

    // fc3 -> class output
    fc3_kernel<<<(B_ * C3_ + 255) / 256, 256>>>(c2, fc3_w, fc3_b, d_out + OUT_CLASS_OFF);

    // fc4 (split-K=16) + relu
    hs_gemm<<<dim3(R1_ / 128, B_ / 128, 16), 512, HS_SMEM>>>(
        fh, f4h, part, nullptr, nullptr, B_, R1_, HT, HT / 16, 0);
    reduce_bias_act<<<(B_ * R1_ + 255) / 256, 256>>>(part, 16, B_ * R1_, R1_, fc4_b, r, 1);

    // fc5 (fp32 path, N=200 ragged) -> regression output
    sgemm_nt<<<dim3((T_ + 127) / 128, B_ / 128, 4), 256>>>(r, fc5_w, part, B_, T_, R1_, R1_ / 4);
    reduce_bias_act<<<(B_ * T_ + 255) / 256, 256>>>(part, 4, B_ * T_, T_, fc5_b,
                                                    d_out + OUT_REG_OFF, 0);
}

// round 14
// speedup vs baseline: 2.0899x; 1.0857x over previous
#include <cuda_runtime.h>
#include <cuda_fp16.h>
#include <math.h>
#include <stdint.h>

// ---------------- problem constants ----------------
constexpr int B_  = 512;
constexpr int T_  = 200;
constexpr int D_  = 64;
constexpr int H_  = 256;
constexpr int BT  = B_ * T_;        // 102400 rows
constexpr int HT  = H_ * T_;        // 51200 flat dim
constexpr int C1_ = 1024;
constexpr int C2_ = 256;
constexpr int C3_ = 10;
constexpr int R1_ = 1024;
constexpr int G3  = 768;            // packed gates i,g,o (forget gate dead, c0=0)

constexpr size_t OUT_TOTAL_OFF = 0;
constexpr size_t OUT_CLASS_OFF = (size_t)BT * H_;
constexpr size_t OUT_REG_OFF   = OUT_CLASS_OFF + (size_t)B_ * C3_;

// ---------------- device scratch ----------------
__device__ __half g_w0h[G3 * D_];           // packed i,g,o rows fp16
__device__ __half g_w1h[G3 * H_];
__device__ float  g_bsel0[G3], g_bsel1[G3];
__device__ __half g_xh [(size_t)BT * D_];   // fp16 input
__device__ __half g_h0h[(size_t)BT * H_];   // fp16 h0
__device__ __half g_fh [(size_t)BT * H_];   // fp16 flat (out_total)
__device__ __half g_f1h[(size_t)C1_ * HT];  // fp16 fc1 weights
__device__ __half g_f4h[(size_t)R1_ * HT];  // fp16 fc4 weights
__device__ float  g_part[16 * 512 * 1024];  // split-K partials
__device__ float  g_c1[B_ * C1_];
__device__ float  g_c2[B_ * C2_];
__device__ float  g_r [B_ * R1_];

// ---------------- PTX helpers (sm_80-compatible only) ----------------
__device__ __forceinline__ uint32_t smem_u32(const void* p) {
    uint32_t a;
    asm("{ .reg .u64 t; cvta.to.shared.u64 t, %1; cvt.u32.u64 %0, t; }" : "=r"(a) : "l"(p));
    return a;
}
__device__ __forceinline__ void cp_async16(uint32_t dst, const void* src) {
    asm volatile("cp.async.cg.shared.global [%0], [%1], 16;" :: "r"(dst), "l"(src));
}
#define CP_COMMIT() asm volatile("cp.async.commit_group;" ::: "memory")
template <int N>
__device__ __forceinline__ void cp_wait() {
    asm volatile("cp.async.wait_group %0;" :: "n"(N) : "memory");
}
__device__ __forceinline__ void ldsm_x4(uint32_t* r, uint32_t addr) {
    asm volatile("ldmatrix.sync.aligned.m8n8.x4.shared.b16 {%0,%1,%2,%3}, [%4];"
                 : "=r"(r[0]), "=r"(r[1]), "=r"(r[2]), "=r"(r[3]) : "r"(addr));
}
__device__ __forceinline__ void mma_f16(float* c, const uint32_t* a, const uint32_t* b) {
    asm volatile("mma.sync.aligned.m16n8k16.row.col.f32.f16.f16.f32 "
                 "{%0,%1,%2,%3}, {%4,%5,%6,%7}, {%8,%9}, {%0,%1,%2,%3};"
                 : "+f"(c[0]), "+f"(c[1]), "+f"(c[2]), "+f"(c[3])
                 : "r"(a[0]), "r"(a[1]), "r"(a[2]), "r"(a[3]), "r"(b[0]), "r"(b[1]));
}
__device__ __forceinline__ uint32_t pack_h2(float a, float b) {
    __half2 t = __floats2half2_rn(a, b);
    return *reinterpret_cast<uint32_t*>(&t);
}
__device__ __forceinline__ float sigm(float x) { return 1.f / (1.f + expf(-x)); }

constexpr int HS_ROWB  = 144;               // 64 fp16 + 8 pad, bytes
constexpr int HS_TILE  = 128 * HS_ROWB;     // 18432
constexpr int HS_STAGE = 2 * HS_TILE;       // 36864 (A | B)
constexpr int HS_SMEM  = 3 * HS_STAGE;      // 110592

// ---------------- gate-mode fp16 GEMM (LSTM layers) — R12 validated ----------------
// g in {i,g,o}: acc_g = A * Wsel[g*256+n,:]^T + bias; h via register stash;
// writes fp16 outH plus optional fp32 C.
// Tile 128x128x64, 512 threads, warp grid 4x4, warp tile 32x32, 3-stage cp.async.
__global__ void __launch_bounds__(512, 1)
hs_gate(const __half* __restrict__ A, const __half* __restrict__ Bw,
        float* __restrict__ C, const float* __restrict__ bias,
        __half* __restrict__ outH, int M, int K)
{
    extern __shared__ __align__(128) char smem[];
    const uint32_t sBase = smem_u32(smem);

    const int tid  = threadIdx.x;
    const int lane = tid & 31;
    const int warp = tid >> 5;
    const int wm   = warp >> 2;              // 0..3
    const int wn   = warp & 3;               // 0..3
    const int mBase = blockIdx.y * 128;
    const int nBase = blockIdx.x * 128;
    const int NC    = K >> 6;

    const int aRow  = (lane & 7) + ((lane >> 3) & 1) * 8;
    const int aCol  = (lane >> 4) * 8;
    const int bRow4 = ((lane >> 4) & 1) * 8 + (lane & 7);
    const int bColH = ((lane >> 3) & 1) * 8;

    const int lrow0 = tid >> 3;              // 0..63
    const int lrow1 = lrow0 + 64;
    const int lc8   = tid & 7;

    float stash[2][4][4];

    for (int g = 0; g < 3; g++) {
        const int rowOff = g * 256 + nBase;

        float acc[2][4][4];
#pragma unroll
        for (int mi = 0; mi < 2; mi++)
#pragma unroll
            for (int ni = 0; ni < 4; ni++)
#pragma unroll
                for (int q = 0; q < 4; q++) acc[mi][ni][q] = 0.f;

        auto prefetch = [&](int c) {
            if (c < NC) {
                int kk = c * 64;
                uint32_t st = sBase + (c % 3) * HS_STAGE;
                cp_async16(st + lrow0 * HS_ROWB + lc8 * 16,
                           A + (size_t)(mBase + lrow0) * K + kk + lc8 * 8);
                cp_async16(st + lrow1 * HS_ROWB + lc8 * 16,
                           A + (size_t)(mBase + lrow1) * K + kk + lc8 * 8);
                cp_async16(st + HS_TILE + lrow0 * HS_ROWB + lc8 * 16,
                           Bw + (size_t)(rowOff + lrow0) * K + kk + lc8 * 8);
                cp_async16(st + HS_TILE + lrow1 * HS_ROWB + lc8 * 16,
                           Bw + (size_t)(rowOff + lrow1) * K + kk + lc8 * 8);
            }
            CP_COMMIT();
        };

        prefetch(0); prefetch(1); prefetch(2);

        for (int c = 0; c < NC; c++) {
            cp_wait<2>();
            __syncthreads();

            uint32_t sA = sBase + (c % 3) * HS_STAGE;
            uint32_t sB = sA + HS_TILE;
#pragma unroll
            for (int ks = 0; ks < 4; ks++) {
                uint32_t ah[2][4], bh[2][4];
#pragma unroll
                for (int mi = 0; mi < 2; mi++) {
                    uint32_t ro = (wm * 32 + mi * 16 + aRow) * HS_ROWB + (ks * 16 + aCol) * 2;
                    ldsm_x4(ah[mi], sA + ro);
                }
#pragma unroll
                for (int p = 0; p < 2; p++) {
                    uint32_t ro = (wn * 32 + p * 16 + bRow4) * HS_ROWB + (ks * 16 + bColH) * 2;
                    ldsm_x4(bh[p], sB + ro);
                }
#pragma unroll
                for (int mi = 0; mi < 2; mi++)
#pragma unroll
                    for (int ni = 0; ni < 4; ni++)
                        mma_f16(acc[mi][ni], ah[mi], &bh[ni >> 1][(ni & 1) * 2]);
            }
            __syncthreads();
            prefetch(c + 3);
        }

#pragma unroll
        for (int mi = 0; mi < 2; mi++)
#pragma unroll
            for (int ni = 0; ni < 4; ni++)
#pragma unroll
                for (int q = 0; q < 4; q++) {
                    int rl = wm * 32 + mi * 16 + (lane >> 2) + ((q >= 2) ? 8 : 0);
                    int cl = wn * 32 + ni * 8 + (lane & 3) * 2 + (q & 1);
                    float v = acc[mi][ni][q] + bias[rowOff + cl];
                    if (g == 0)      stash[mi][ni][q] = sigm(v);
                    else if (g == 1) stash[mi][ni][q] *= tanhf(v);
                    else {
                        float h = sigm(v) * tanhf(stash[mi][ni][q]);
                        size_t o = (size_t)(mBase + rl) * H_ + nBase + cl;
                        if (C) C[o] = h;
                        outH[o] = __float2half(h);
                    }
                }
    }
}

// ---------------- fc fp16 GEMM: 64x32 warp tile, 2 CTAs/SM ----------------
// C[z][M,N] partial = A[M,K] * B[N,K]^T over k-slice z.
// Tile 128x128x64, 256 threads, warp grid 2x4, warp tile 64x32, 3-stage cp.async.
__global__ void __launch_bounds__(256, 2)
hs_fc(const __half* __restrict__ A, const __half* __restrict__ Bw,
      float* __restrict__ C, int M, int N, int K, int kSlice)
{
    extern __shared__ __align__(128) char smem[];
    const uint32_t sBase = smem_u32(smem);

    const int tid  = threadIdx.x;
    const int lane = tid & 31;
    const int warp = tid >> 5;               // 0..7
    const int wm   = warp >> 2;              // 0..1 (64 M-rows each)
    const int wn   = warp & 3;               // 0..3 (32 N-cols each)
    const int mBase = blockIdx.y * 128;
    const int nBase = blockIdx.x * 128;
    const int z     = blockIdx.z;
    const int kBeg  = z * kSlice;
    const int NC    = kSlice >> 6;

    const int aRow  = (lane & 7) + ((lane >> 3) & 1) * 8;
    const int aCol  = (lane >> 4) * 8;
    const int bRow4 = ((lane >> 4) & 1) * 8 + (lane & 7);
    const int bColH = ((lane >> 3) & 1) * 8;

    // loader: per tile 1024 x 16B chunks, 4 per thread per tile
    const int lc8 = tid & 7;
    int lrw[4];
#pragma unroll
    for (int t = 0; t < 4; t++) lrw[t] = (tid + t * 256) >> 3;   // 0..127

    float acc[4][4][4];
#pragma unroll
    for (int mi = 0; mi < 4; mi++)
#pragma unroll
        for (int ni = 0; ni < 4; ni++)
#pragma unroll
            for (int q = 0; q < 4; q++) acc[mi][ni][q] = 0.f;

    auto prefetch = [&](int c) {
        if (c < NC) {
            int kk = kBeg + c * 64;
            uint32_t st = sBase + (c % 3) * HS_STAGE;
#pragma unroll
            for (int t = 0; t < 4; t++) {
                cp_async16(st + lrw[t] * HS_ROWB + lc8 * 16,
                           A + (size_t)(mBase + lrw[t]) * K + kk + lc8 * 8);
                cp_async16(st + HS_TILE + lrw[t] * HS_ROWB + lc8 * 16,
                           Bw + (size_t)(nBase + lrw[t]) * K + kk + lc8 * 8);
            }
        }
        CP_COMMIT();
    };

    prefetch(0); prefetch(1); prefetch(2);

    for (int c = 0; c < NC; c++) {
        cp_wait<2>();
        __syncthreads();

        uint32_t sA = sBase + (c % 3) * HS_STAGE;
        uint32_t sB = sA + HS_TILE;
#pragma unroll
        for (int ks = 0; ks < 4; ks++) {
            uint32_t ah[4][4], bh[2][4];
#pragma unroll
            for (int mi = 0; mi < 4; mi++) {
                uint32_t ro = (wm * 64 + mi * 16 + aRow) * HS_ROWB + (ks * 16 + aCol) * 2;
                ldsm_x4(ah[mi], sA + ro);
            }
#pragma unroll
            for (int p = 0; p < 2; p++) {
                uint32_t ro = (wn * 32 + p * 16 + bRow4) * HS_ROWB + (ks * 16 + bColH) * 2;
                ldsm_x4(bh[p], sB + ro);
            }
#pragma unroll
            for (int mi = 0; mi < 4; mi++)
#pragma unroll
                for (int ni = 0; ni < 4; ni++)
                    mma_f16(acc[mi][ni], ah[mi], &bh[ni >> 1][(ni & 1) * 2]);
        }
        __syncthreads();
        prefetch(c + 3);
    }

    float* Cp = C + (size_t)z * M * N;
#pragma unroll
    for (int mi = 0; mi < 4; mi++) {
        int r0 = mBase + wm * 64 + mi * 16 + (lane >> 2);
#pragma unroll
        for (int ni = 0; ni < 4; ni++) {
            int col = nBase + wn * 32 + ni * 8 + (lane & 3) * 2;
            *reinterpret_cast<float2*>(&Cp[(size_t)r0 * N + col]) =
                make_float2(acc[mi][ni][0], acc[mi][ni][1]);
            *reinterpret_cast<float2*>(&Cp[(size_t)(r0 + 8) * N + col]) =
                make_float2(acc[mi][ni][2], acc[mi][ni][3]);
        }
    }
}

// ---------------- prep kernels ----------------
__global__ void cvt_f16(const float4* __restrict__ src, uint2* __restrict__ dst, int n4)
{
    int i = blockIdx.x * blockDim.x + threadIdx.x;
    if (i >= n4) return;
    float4 v = src[i];
    dst[i] = make_uint2(pack_h2(v.x, v.y), pack_h2(v.z, v.w));
}

__global__ void make_wsel_f16(const float* __restrict__ W, const float* __restrict__ bih,
                              const float* __restrict__ bhh, __half* __restrict__ Wh,
                              float* __restrict__ bsel, int Kd)
{
    int idx = blockIdx.x * blockDim.x + threadIdx.x;
    int total = G3 * Kd;
    if (idx < total) {
        int j = idx / Kd;
        int c = idx - j * Kd;
        int src = j + ((j >= 256) ? 256 : 0);
        Wh[idx] = __float2half(W[src * Kd + c]);
    }
    if (idx < G3) {
        int src = idx + ((idx >= 256) ? 256 : 0);
        bsel[idx] = bih[src] + bhh[src];
    }
}

__global__ void reduce_bias_act(const float* __restrict__ part, int S, int MN, int N,
                                const float* __restrict__ bias, float* __restrict__ out, int relu)
{
    int idx = blockIdx.x * blockDim.x + threadIdx.x;
    if (idx >= MN) return;
    float s = 0.f;
    for (int i = 0; i < S; i++) s += part[(size_t)i * MN + idx];
    s += bias[idx % N];
    if (relu) s = fmaxf(s, 0.f);
    out[idx] = s;
}

// ---------------- fp32 SGEMM (small fc layers) ----------------
__global__ void __launch_bounds__(256, 2)
sgemm_nt(const float* __restrict__ A, const float* __restrict__ B,
         float* __restrict__ C, int M, int N, int K, int kSlice)
{
    constexpr int BM = 128, BN = 128, BK = 8;
    __shared__ float As[BK][BM];
    __shared__ float Bs[BK][BN];
    const int tid = threadIdx.x;
    const int mBase = blockIdx.y * BM;
    const int nBase = blockIdx.x * BN;
    const int z = blockIdx.z;
    const int kBeg = z * kSlice;
    const int kEnd = kBeg + kSlice;
    const int lr = tid >> 1;
    const int lc = (tid & 1) * 4;
    const int tr = (tid >> 4) * 8;
    const int tc = (tid & 15) * 8;
    float acc[8][8];
#pragma unroll
    for (int i = 0; i < 8; i++)
#pragma unroll
        for (int j = 0; j < 8; j++) acc[i][j] = 0.f;
    const float* Aptr = A + (size_t)(mBase + lr) * K;
    const bool bvalid = (nBase + lr) < N;
    const float* Bptr = B + (bvalid ? (size_t)(nBase + lr) * K : 0);
    for (int k0 = kBeg; k0 < kEnd; k0 += BK) {
        float4 a4 = *reinterpret_cast<const float4*>(Aptr + k0 + lc);
        float4 b4 = make_float4(0.f, 0.f, 0.f, 0.f);
        if (bvalid) b4 = *reinterpret_cast<const float4*>(Bptr + k0 + lc);
        As[lc + 0][lr] = a4.x; As[lc + 1][lr] = a4.y;
        As[lc + 2][lr] = a4.z; As[lc + 3][lr] = a4.w;
        Bs[lc + 0][lr] = b4.x; Bs[lc + 1][lr] = b4.y;
        Bs[lc + 2][lr] = b4.z; Bs[lc + 3][lr] = b4.w;
        __syncthreads();
#pragma unroll
        for (int kk = 0; kk < BK; kk++) {
            float rm[8], rn[8];
#pragma unroll
            for (int i = 0; i < 8; i++) rm[i] = As[kk][tr + i];
#pragma unroll
            for (int j = 0; j < 8; j++) rn[j] = Bs[kk][tc + j];
#pragma unroll
            for (int i = 0; i < 8; i++)
#pragma unroll
                for (int j = 0; j < 8; j++) acc[i][j] = fmaf(rm[i], rn[j], acc[i][j]);
        }
        __syncthreads();
    }
    float* Cp = C + (size_t)z * M * N;
#pragma unroll
    for (int i = 0; i < 8; i++) {
        const size_t rowOff = (size_t)(mBase + tr + i) * N;
#pragma unroll
        for (int j = 0; j < 8; j++) {
            int col = nBase + tc + j;
            if (col < N) Cp[rowOff + col] = acc[i][j];
        }
    }
}

__global__ void fc3_kernel(const float* __restrict__ x, const float* __restrict__ W,
                           const float* __restrict__ b, float* __restrict__ out)
{
    int idx = blockIdx.x * blockDim.x + threadIdx.x;
    if (idx >= B_ * C3_) return;
    int m = idx / C3_;
    int n = idx - m * C3_;
    const float* xr = x + m * C2_;
    const float* wr = W + n * C2_;
    float s = 0.f;
#pragma unroll 4
    for (int k = 0; k < C2_; k++) s = fmaf(xr[k], wr[k], s);
    out[idx] = s + b[n];
}

// ---------------- launch ----------------
extern "C" void kernel_launch(void* const* d_in, const int* in_sizes, int n_in,
                              void* d_out_v, int out_size)
{
    const float* x     = (const float*)d_in[0];
    const float* W_ih0 = (const float*)d_in[1];
    const float* b_ih0 = (const float*)d_in[2];
    const float* b_hh0 = (const float*)d_in[3];
    const float* W_ih1 = (const float*)d_in[4];
    const float* b_ih1 = (const float*)d_in[5];
    const float* b_hh1 = (const float*)d_in[6];
    const float* fc1_w = (const float*)d_in[7];
    const float* fc1_b = (const float*)d_in[8];
    const float* fc2_w = (const float*)d_in[9];
    const float* fc2_b = (const float*)d_in[10];
    const float* fc3_w = (const float*)d_in[11];
    const float* fc3_b = (const float*)d_in[12];
    const float* fc4_w = (const float*)d_in[13];
    const float* fc4_b = (const float*)d_in[14];
    const float* fc5_w = (const float*)d_in[15];
    const float* fc5_b = (const float*)d_in[16];
    float* d_out = (float*)d_out_v;

    cudaFuncSetAttribute(hs_gate, cudaFuncAttributeMaxDynamicSharedMemorySize, HS_SMEM);
    cudaFuncSetAttribute(hs_fc,   cudaFuncAttributeMaxDynamicSharedMemorySize, HS_SMEM);

    __half *w0h, *w1h, *xh, *h0h, *fh, *f1h, *f4h;
    float *bsel0, *bsel1, *part, *c1, *c2, *r;
    cudaGetSymbolAddress((void**)&w0h, g_w0h);
    cudaGetSymbolAddress((void**)&w1h, g_w1h);
    cudaGetSymbolAddress((void**)&bsel0, g_bsel0);
    cudaGetSymbolAddress((void**)&bsel1, g_bsel1);
    cudaGetSymbolAddress((void**)&xh,  g_xh);
    cudaGetSymbolAddress((void**)&h0h, g_h0h);
    cudaGetSymbolAddress((void**)&fh,  g_fh);
    cudaGetSymbolAddress((void**)&f1h, g_f1h);
    cudaGetSymbolAddress((void**)&f4h, g_f4h);
    cudaGetSymbolAddress((void**)&part, g_part);
    cudaGetSymbolAddress((void**)&c1, g_c1);
    cudaGetSymbolAddress((void**)&c2, g_c2);
    cudaGetSymbolAddress((void**)&r,  g_r);

    // prep: pack gate weights fp16 + convert x / fc weights to fp16 (one-time)
    make_wsel_f16<<<(G3 * D_ + 255) / 256, 256>>>(W_ih0, b_ih0, b_hh0, w0h, bsel0, D_);
    make_wsel_f16<<<(G3 * H_ + 255) / 256, 256>>>(W_ih1, b_ih1, b_hh1, w1h, bsel1, H_);
    cvt_f16<<<(BT * D_ / 4 + 255) / 256, 256>>>((const float4*)x, (uint2*)xh, BT * D_ / 4);
    cvt_f16<<<(C1_ * HT / 4 + 255) / 256, 256>>>((const float4*)fc1_w, (uint2*)f1h, C1_ * HT / 4);
    cvt_f16<<<(R1_ * HT / 4 + 255) / 256, 256>>>((const float4*)fc4_w, (uint2*)f4h, R1_ * HT / 4);

    // LSTM layer 0 (gate mode): h0 fp16 = lstm(x @ Wsel0^T + bsel0)
    hs_gate<<<dim3(2, BT / 128, 1), 512, HS_SMEM>>>(
        xh, w0h, nullptr, bsel0, h0h, BT, D_);

    // LSTM layer 1 (gate mode): out_total fp32 -> d_out, flat fp16 -> fh
    hs_gate<<<dim3(2, BT / 128, 1), 512, HS_SMEM>>>(
        h0h, w1h, d_out + OUT_TOTAL_OFF, bsel1, fh, BT, H_);

    // fc1 (split-K=16) + relu
    hs_fc<<<dim3(C1_ / 128, B_ / 128, 16), 256, HS_SMEM>>>(
        fh, f1h, part, B_, C1_, HT, HT / 16);
    reduce_bias_act<<<(B_ * C1_ + 255) / 256, 256>>>(part, 16, B_ * C1_, C1_, fc1_b, c1, 1);

    // fc2 (fp32 path) + relu
    sgemm_nt<<<dim3(C2_ / 128, B_ / 128, 4), 256>>>(c1, fc2_w, part, B_, C2_, C1_, C1_ / 4);
    reduce_bias_act<<<(B_ * C2_ + 255) / 256, 256>>>(part, 4, B_ * C2_, C2_, fc2_b, c2, 1);

    // fc3 -> class output
    fc3_kernel<<<(B_ * C3_ + 255) / 256, 256>>>(c2, fc3_w, fc3_b, d_out + OUT_CLASS_OFF);

    // fc4 (split-K=16) + relu
    hs_fc<<<dim3(R1_ / 128, B_ / 128, 16), 256, HS_SMEM>>>(
        fh, f4h, part, B_, R1_, HT, HT / 16);
    reduce_bias_act<<<(B_ * R1_ + 255) / 256, 256>>>(part, 16, B_ * R1_, R1_, fc4_b, r, 1);

    // fc5 (fp32 path, N=200 ragged) -> regression output
    sgemm_nt<<<dim3((T_ + 127) / 128, B_ / 128, 4), 256>>>(r, fc5_w, part, B_, T_, R1_, R1_ / 4);
    reduce_bias_act<<<(B_ * T_ + 255) / 256, 256>>>(part, 4, B_ * T_, T_, fc5_b,
                                                    d_out + OUT_REG_OFF, 0);
}